// round 8
// baseline (speedup 1.0000x reference)
#include <cuda_runtime.h>
#include <math.h>

// ---------------- problem constants ----------------
#define BATCH      32768
#define TILE_B     64
#define NTHREADS   256
#define HORIZON_T  64

// smem layout (in floats)
#define OFF_AH0   0
#define OFF_AH1   16384                 // 64*256 floats
#define OFF_BSH   32768                 // 2 bufs * 8 kp2-rows * 256 n * 16B = 64KB
#define OFF_W1    49152                 // 4 kp2-rows * 256 n * 16B = 16KB
#define OFF_WMU   53248                 // 2*256
#define OFF_B1    53760
#define OFF_B2    54016
#define OFF_B3    54272
#define OFF_BMU   54528
#define SMEM_FLOATS 54532
#define SMEM_BYTES  (SMEM_FLOATS * 4)

// ---------------- packed f32x2 helpers ----------------
__device__ __forceinline__ unsigned long long pk2(float x, float y) {
    unsigned long long r;
    asm("mov.b64 %0, {%1, %2};" : "=l"(r) : "f"(x), "f"(y));
    return r;
}
__device__ __forceinline__ void upk2(unsigned long long v, float& x, float& y) {
    asm("mov.b64 {%0, %1}, %2;" : "=f"(x), "=f"(y) : "l"(v));
}
__device__ __forceinline__ void ffma2(unsigned long long& d,
                                      unsigned long long a,
                                      unsigned long long b) {
    asm("fma.rn.f32x2 %0, %1, %2, %0;" : "+l"(d) : "l"(a), "l"(b));
}

// ---------------- GEMM tile: 64(m) x 256(n), 8 warps, 8m x 8n per thread ----
// warp w owns m rows [8w, 8w+8); lane l owns n cols {l + 32j, j=0..7}.
// acc lanes = (even k, odd k). B layout: ulonglong2 per (kp2, n):
//   .x = pk2(k0,k1), .y = pk2(k2,k3) for k = 4*kp2 + {0..3} within chunk.
template <int KPC2, int APITCH, int UNR>
__device__ __forceinline__ void mma_tile(unsigned long long acc[8][8],
                                         const float* __restrict__ A,
                                         const ulonglong2* __restrict__ B,
                                         int w, int l) {
    const float* Aw = A + (w * 8) * APITCH;
#pragma unroll UNR
    for (int kp2 = 0; kp2 < KPC2; ++kp2) {
        ulonglong2 a2[8];
#pragma unroll
        for (int i = 0; i < 8; ++i)
            a2[i] = *reinterpret_cast<const ulonglong2*>(Aw + i * APITCH + 4 * kp2);
        const ulonglong2* Brow = B + kp2 * 256 + l;
        ulonglong2 b2[8];
#pragma unroll
        for (int j = 0; j < 8; ++j) b2[j] = Brow[32 * j];
#pragma unroll
        for (int i = 0; i < 8; ++i)
#pragma unroll
            for (int j = 0; j < 8; ++j) {
                ffma2(acc[i][j], a2[i].x, b2[j].x);
                ffma2(acc[i][j], a2[i].y, b2[j].y);
            }
    }
}

__device__ __forceinline__ void zero_acc(unsigned long long acc[8][8]) {
#pragma unroll
    for (int i = 0; i < 8; ++i)
#pragma unroll
        for (int j = 0; j < 8; ++j) acc[i][j] = 0ull;
}

__device__ __forceinline__ void epilogue_relu(unsigned long long acc[8][8],
                                              float* __restrict__ out,
                                              const float* __restrict__ bias,
                                              int w, int l) {
#pragma unroll
    for (int i = 0; i < 8; ++i) {
        float* orow = out + (w * 8 + i) * 256;
#pragma unroll
        for (int j = 0; j < 8; ++j) {
            int n = l + 32 * j;
            float x, y;
            upk2(acc[i][j], x, y);
            float c = x + y + bias[n];
            orow[n] = fmaxf(c, 0.0f);
        }
    }
}

// stage a 32-k chunk of a 256x256 k-major weight into paired-kp2 layout.
__device__ __forceinline__ void stage32(ulonglong2* __restrict__ Bsh,
                                        const float* __restrict__ W,
                                        int k0, int tid) {
    const float* Wc = W + tid;
#pragma unroll
    for (int r = 0; r < 8; ++r) {
        int k = k0 + 4 * r;
        float x0 = Wc[(k + 0) * 256];
        float x1 = Wc[(k + 1) * 256];
        float x2 = Wc[(k + 2) * 256];
        float x3 = Wc[(k + 3) * 256];
        ulonglong2 v;
        v.x = pk2(x0, x1);
        v.y = pk2(x2, x3);
        Bsh[r * 256 + tid] = v;
    }
}

// ---------------- main kernel ----------------
__global__ void __launch_bounds__(NTHREADS, 1)
rollout_kernel(const float* __restrict__ pos0, const float* __restrict__ wind,
               const float* __restrict__ w1, const float* __restrict__ b1,
               const float* __restrict__ w2, const float* __restrict__ b2,
               const float* __restrict__ w3, const float* __restrict__ b3,
               const float* __restrict__ wmu, const float* __restrict__ bmu,
               float* __restrict__ out) {
    extern __shared__ float smem[];
    float* Ah0 = smem + OFF_AH0;
    float* Ah1 = smem + OFF_AH1;
    ulonglong2* Bsh  = reinterpret_cast<ulonglong2*>(smem + OFF_BSH);
    ulonglong2* W1sh = reinterpret_cast<ulonglong2*>(smem + OFF_W1);
    float* wmu_s = smem + OFF_WMU;
    float* b1s = smem + OFF_B1;
    float* b2s = smem + OFF_B2;
    float* b3s = smem + OFF_B3;
    float* bmu_s = smem + OFF_BMU;

    const int tid = threadIdx.x;
    const int w = tid >> 5;
    const int l = tid & 31;

    b1s[tid] = b1[tid];
    b2s[tid] = b2[tid];
    b3s[tid] = b3[tid];
    for (int idx = tid; idx < 512; idx += NTHREADS) {
        int c = idx >> 8, k = idx & 255;
        wmu_s[idx] = wmu[k * 2 + c];
    }
    if (tid < 2) bmu_s[tid] = bmu[tid];
#pragma unroll
    for (int i = 0; i < 4; ++i) {
        float v[4];
#pragma unroll
        for (int q = 0; q < 4; ++q) {
            int k = 4 * i + q;
            v[q] = (k < 13) ? w1[k * 256 + tid] : 0.0f;
        }
        ulonglong2 e;
        e.x = pk2(v[0], v[1]);
        e.y = pk2(v[2], v[3]);
        W1sh[i * 256 + tid] = e;
    }

    const bool owner = (tid < 128) && ((tid & 1) == 0);
    const int m = tid >> 1;
    const int bidx = blockIdx.x * TILE_B + m;
    float px = 0.f, py = 0.f, wx = 0.f, wy = 0.f;
    float msafe = -INFINITY, ssafe = 0.f, mreach = -INFINITY, sreach = 0.f;
    if (owner) {
        px = pos0[2 * bidx]; py = pos0[2 * bidx + 1];
        wx = wind[2 * bidx]; wy = wind[2 * bidx + 1];
    }

    const float ox0 = 1.75f, oy0 = 1.75f, r0 = 0.38f;
    const float ox1 = 1.75f, oy1 = 3.75f, r1 = 0.42f;
    const float ox2 = 3.75f, oy2 = 2.00f, r2 = 0.34f;

    // prologue: stage w2 chunk 0 into buf0
    stage32(Bsh, w2, 0, tid);
    __syncthreads();

    unsigned long long acc[8][8];

    for (int t = 0; t < HORIZON_T; ++t) {
        if (owner) {
            float* o = Ah0 + m * 16;
            o[0] = px * 0.1f;
            o[1] = py * 0.1f;
            o[2] = (4.0f - px) * 0.1f;
            o[3] = (3.0f - py) * 0.1f;
            float dx0 = px - ox0, dy0 = py - oy0;
            float dx1 = px - ox1, dy1 = py - oy1;
            float dx2 = px - ox2, dy2 = py - oy2;
            float d0 = sqrtf(dx0 * dx0 + dy0 * dy0 + 1e-9f);
            float d1 = sqrtf(dx1 * dx1 + dy1 * dy1 + 1e-9f);
            float d2 = sqrtf(dx2 * dx2 + dy2 * dy2 + 1e-9f);
            o[4] = -dx0 * 0.1f; o[5] = -dy0 * 0.1f;
            o[6] = -dx1 * 0.1f; o[7] = -dy1 * 0.1f;
            o[8] = -dx2 * 0.1f; o[9] = -dy2 * 0.1f;
            o[10] = d0 - r0; o[11] = d1 - r1; o[12] = d2 - r2;
            o[13] = 0.f; o[14] = 0.f; o[15] = 0.f;
        }
        __syncthreads();

        // layer 1
        zero_acc(acc);
        mma_tile<4, 16, 4>(acc, Ah0, W1sh, w, l);
        epilogue_relu(acc, Ah1, b1s, w, l);

        // layer 2: 8 chunks of 32k, double-buffered; tail stages w3 chunk0
        zero_acc(acc);
#pragma unroll 1
        for (int c = 0; c < 8; ++c) {
            ulonglong2* nbuf = Bsh + ((c + 1) & 1) * 2048;
            if (c < 7) stage32(nbuf, w2, (c + 1) * 32, tid);
            else       stage32(nbuf, w3, 0, tid);
            mma_tile<8, 256, 2>(acc, Ah1 + c * 32, Bsh + (c & 1) * 2048, w, l);
            __syncthreads();
        }
        epilogue_relu(acc, Ah0, b2s, w, l);

        // layer 3: tail stages w2 chunk0 for next step
        zero_acc(acc);
#pragma unroll 1
        for (int c = 0; c < 8; ++c) {
            ulonglong2* nbuf = Bsh + ((c + 1) & 1) * 2048;
            if (c < 7) stage32(nbuf, w3, (c + 1) * 32, tid);
            else       stage32(nbuf, w2, 0, tid);
            mma_tile<8, 256, 2>(acc, Ah0 + c * 32, Bsh + (c & 1) * 2048, w, l);
            __syncthreads();
        }
        epilogue_relu(acc, Ah1, b3s, w, l);
        __syncthreads();

        // layer 4
        float act0 = 0.f, act1 = 0.f;
        if (tid < 128) {
            int mm = tid >> 1, cc = tid & 1;
            const float4* hrow = reinterpret_cast<const float4*>(Ah1 + mm * 256);
            const float4* wrow = reinterpret_cast<const float4*>(wmu_s + cc * 256);
            float accd = bmu_s[cc];
#pragma unroll 8
            for (int ii = 0; ii < 64; ++ii) {
                int idx = (ii + mm) & 63;
                float4 h4 = hrow[idx];
                float4 w4 = wrow[idx];
                accd = fmaf(h4.x, w4.x, accd);
                accd = fmaf(h4.y, w4.y, accd);
                accd = fmaf(h4.z, w4.z, accd);
                accd = fmaf(h4.w, w4.w, accd);
            }
            float other = __shfl_xor_sync(0xffffffffu, accd, 1);
            if (cc == 0) { act0 = accd; act1 = other; }
        }

        if (owner) {
            float ax = fminf(fmaxf(act0, -1.0f), 1.0f);
            float ay = fminf(fmaxf(act1, -1.0f), 1.0f);
            float vx = 2.0f * ax + wx;
            float vy = 2.0f * ay + wy;
#pragma unroll
            for (int s = 0; s < 4; ++s) {
                px = fminf(fmaxf(px + 0.0625f * vx, -4.0f), 10.0f);
                py = fminf(fmaxf(py + 0.0625f * vy, -4.0f), 10.0f);
            }
            float dx0 = px - ox0, dy0 = py - oy0;
            float dx1 = px - ox1, dy1 = py - oy1;
            float dx2 = px - ox2, dy2 = py - oy2;
            float c0 = sqrtf(dx0 * dx0 + dy0 * dy0 + 1e-9f) - r0;
            float c1 = sqrtf(dx1 * dx1 + dy1 * dy1 + 1e-9f) - r1;
            float c2 = sqrtf(dx2 * dx2 + dy2 * dy2 + 1e-9f) - r2;
            float v0 = -50.0f * c0, v1 = -50.0f * c1, v2 = -50.0f * c2;
            float vm = fmaxf(v0, fmaxf(v1, v2));
            float lse = vm + logf(expf(v0 - vm) + expf(v1 - vm) + expf(v2 - vm));
            float safe = -lse / 50.0f;
            float vs = -8.0f * safe;
            if (vs > msafe) { ssafe = ssafe * expf(msafe - vs) + 1.0f; msafe = vs; }
            else            { ssafe += expf(vs - msafe); }
            float gdx = px - 4.0f, gdy = py - 3.0f;
            float gd = sqrtf(gdx * gdx + gdy * gdy + 1e-9f);
            float vr = 8.0f * (0.45f - gd);
            if (vr > mreach) { sreach = sreach * expf(mreach - vr) + 1.0f; mreach = vr; }
            else             { sreach += expf(vr - mreach); }
        }
    }

    if (owner) {
        float rs = -(msafe + logf(ssafe)) * 0.125f;
        float rr =  (mreach + logf(sreach)) * 0.125f;
        float u0 = -8.0f * rs, u1 = -8.0f * rr;
        float um = fmaxf(u0, u1);
        float rho = -(um + logf(expf(u0 - um) + expf(u1 - um))) * 0.125f;
        out[bidx] = rho;
    }
}

extern "C" void kernel_launch(void* const* d_in, const int* in_sizes, int n_in,
                              void* d_out, int out_size) {
    const float* pos0 = (const float*)d_in[0];
    const float* wind = (const float*)d_in[1];
    const float* w1   = (const float*)d_in[2];
    const float* b1   = (const float*)d_in[3];
    const float* w2   = (const float*)d_in[4];
    const float* b2   = (const float*)d_in[5];
    const float* w3   = (const float*)d_in[6];
    const float* b3   = (const float*)d_in[7];
    const float* wmu  = (const float*)d_in[8];
    const float* bmu  = (const float*)d_in[9];
    float* out = (float*)d_out;

    cudaFuncSetAttribute(rollout_kernel,
                         cudaFuncAttributeMaxDynamicSharedMemorySize, SMEM_BYTES);

    int B = in_sizes[0] / 2;           // 32768
    int grid = B / TILE_B;             // 512
    rollout_kernel<<<grid, NTHREADS, SMEM_BYTES>>>(pos0, wind, w1, b1, w2, b2,
                                                   w3, b3, wmu, bmu, out);
}

// round 10
// speedup vs baseline: 2.9522x; 2.9522x over previous
#include <cuda_runtime.h>
#include <math.h>
#include <stdint.h>

#define NTH 256
#define HOR 64

// ---------------- smem word offsets ----------------
#define APW    132u                 // A row pitch (words); 132 mod 32 = 4 -> conflict-free
#define A_LO_W 16896u               // 128*132
#define BB_W   33792u               // B buffers start
#define BSZ_W  5120u                // 256 rows * 20 words
#define BPW    20u                  // B row pitch words; 20 -> (20g+t) distinct mod 32
#define B1W    54272u
#define B2W    54528u
#define B3W    54784u
#define WMUW   55040u               // [2][256]
#define ACTW   55552u               // 128 float2
#define SMEM_WORDS 55840u
#define SMEM_BYTES (SMEM_WORDS * 4u)

// ---------------- bf16 helpers ----------------
__device__ __forceinline__ uint32_t cvt2(float hi, float lo) {   // pack {hi,lo} -> lo in bits[15:0]
    uint32_t r;
    asm("cvt.rn.bf16x2.f32 %0, %1, %2;" : "=r"(r) : "f"(hi), "f"(lo));
    return r;
}
__device__ __forceinline__ float blo(uint32_t p) { return __uint_as_float(p << 16); }
__device__ __forceinline__ float bhi(uint32_t p) { return __uint_as_float(p & 0xffff0000u); }

__device__ __forceinline__ void mma16816(float& c0, float& c1, float& c2, float& c3,
                                         uint32_t a0, uint32_t a1, uint32_t a2, uint32_t a3,
                                         uint32_t b0, uint32_t b1) {
    asm volatile("mma.sync.aligned.m16n8k16.row.col.f32.bf16.bf16.f32 "
        "{%0,%1,%2,%3}, {%4,%5,%6,%7}, {%8,%9}, {%0,%1,%2,%3};"
        : "+f"(c0), "+f"(c1), "+f"(c2), "+f"(c3)
        : "r"(a0), "r"(a1), "r"(a2), "r"(a3), "r"(b0), "r"(b1));
}

// ---------------- W staging ----------------
__device__ __forceinline__ void ldg32(float* r, const float* __restrict__ W, int k0, int n) {
#pragma unroll
    for (int k = 0; k < 32; ++k) r[k] = __ldg(W + (k0 + k) * 256 + n);
}
__device__ __forceinline__ void ldgw1(float* r, const float* __restrict__ W, int n) {
#pragma unroll
    for (int k = 0; k < 16; ++k) r[k] = (k < 13) ? __ldg(W + k * 256 + n) : 0.0f;
}
template <int NP4>   // NP4 = npairs/4 (4 for 32k chunks, 2 for W1)
__device__ __forceinline__ void sts_pairs(uint32_t* smw, uint32_t hb, uint32_t lb,
                                          const float* r, int n) {
    const uint32_t base = (uint32_t)n * BPW;
#pragma unroll
    for (int i4 = 0; i4 < NP4; ++i4) {
        uint32_t h[4], lo[4];
#pragma unroll
        for (int k = 0; k < 4; ++k) {
            float v0 = r[8 * i4 + 2 * k], v1 = r[8 * i4 + 2 * k + 1];
            uint32_t hh = cvt2(v1, v0);
            h[k] = hh;
            lo[k] = cvt2(v1 - bhi(hh), v0 - blo(hh));
        }
        *reinterpret_cast<uint4*>(smw + hb + base + 4 * i4) = make_uint4(h[0], h[1], h[2], h[3]);
        *reinterpret_cast<uint4*>(smw + lb + base + 4 * i4) = make_uint4(lo[0], lo[1], lo[2], lo[3]);
    }
}

// ---------------- MMA over one k-chunk (NQ k16-tiles) ----------------
template <int NQ>
__device__ __forceinline__ void mma_chunk(float (&c)[32][4], const uint32_t* __restrict__ smw,
                                          uint32_t ah0, uint32_t ah1, uint32_t al0, uint32_t al1,
                                          uint32_t bh, uint32_t bl, int g, int tg) {
#pragma unroll
    for (int q = 0; q < NQ; ++q) {
        const uint32_t aw = 8u * q + (uint32_t)tg;
        uint32_t xh0 = smw[ah0 + aw],     xh1 = smw[ah1 + aw];
        uint32_t xh2 = smw[ah0 + aw + 4], xh3 = smw[ah1 + aw + 4];
        uint32_t xl0 = smw[al0 + aw],     xl1 = smw[al1 + aw];
        uint32_t xl2 = smw[al0 + aw + 4], xl3 = smw[al1 + aw + 4];
#pragma unroll
        for (int j = 0; j < 32; ++j) {
            uint32_t bw = (uint32_t)(8 * j + g) * BPW + 8u * q + (uint32_t)tg;
            uint32_t yh0 = smw[bh + bw], yh1 = smw[bh + bw + 4];
            uint32_t yl0 = smw[bl + bw], yl1 = smw[bl + bw + 4];
            mma16816(c[j][0], c[j][1], c[j][2], c[j][3], xh0, xh1, xh2, xh3, yh0, yh1);
            mma16816(c[j][0], c[j][1], c[j][2], c[j][3], xh0, xh1, xh2, xh3, yl0, yl1);
            mma16816(c[j][0], c[j][1], c[j][2], c[j][3], xl0, xl1, xl2, xl3, yh0, yh1);
        }
    }
}

// h = relu(C + bias) -> A smem (bf16 hi/lo); zero C
__device__ __forceinline__ void epi_h(float (&c)[32][4], const float* __restrict__ smem,
                                      uint32_t* __restrict__ smw, uint32_t bw,
                                      uint32_t ah0, uint32_t ah1, uint32_t al0, uint32_t al1,
                                      int tg) {
#pragma unroll
    for (int j = 0; j < 32; ++j) {
        const int n = 8 * j + 2 * tg;
        float2 bb = *reinterpret_cast<const float2*>(smem + bw + n);
        float v0 = fmaxf(c[j][0] + bb.x, 0.0f), v1 = fmaxf(c[j][1] + bb.y, 0.0f);
        float v2 = fmaxf(c[j][2] + bb.x, 0.0f), v3 = fmaxf(c[j][3] + bb.y, 0.0f);
        uint32_t h01 = cvt2(v1, v0);
        uint32_t l01 = cvt2(v1 - bhi(h01), v0 - blo(h01));
        uint32_t h23 = cvt2(v3, v2);
        uint32_t l23 = cvt2(v3 - bhi(h23), v2 - blo(h23));
        const uint32_t wof = 4u * j + (uint32_t)tg;
        smw[ah0 + wof] = h01;
        smw[ah1 + wof] = h23;
        smw[al0 + wof] = l01;
        smw[al1 + wof] = l23;
        c[j][0] = c[j][1] = c[j][2] = c[j][3] = 0.0f;
    }
}

// ---------------- main kernel ----------------
__global__ void __launch_bounds__(NTH, 1)
rollout_kernel(const float* __restrict__ pos0, const float* __restrict__ wind,
               const float* __restrict__ w1, const float* __restrict__ b1,
               const float* __restrict__ w2, const float* __restrict__ b2,
               const float* __restrict__ w3, const float* __restrict__ b3,
               const float* __restrict__ wmu, const float* __restrict__ bmu,
               float* __restrict__ out) {
    extern __shared__ float smem[];
    uint32_t* smw = reinterpret_cast<uint32_t*>(smem);

    const int tid = threadIdx.x;
    const int w = tid >> 5, l = tid & 31;
    const int g = l >> 2, tg = l & 3;
    const int m0 = 16 * w + g, m1 = m0 + 8;
    const uint32_t AH0 = (uint32_t)m0 * APW, AH1 = (uint32_t)m1 * APW;
    const uint32_t AL0 = AH0 + A_LO_W,       AL1 = AH1 + A_LO_W;

    // constants -> smem
    smem[B1W + tid] = b1[tid];
    smem[B2W + tid] = b2[tid];
    smem[B3W + tid] = b3[tid];
    smem[WMUW + tid]       = wmu[tid * 2];
    smem[WMUW + 256 + tid] = wmu[tid * 2 + 1];
    const float bmu0 = __ldg(bmu), bmu1 = __ldg(bmu + 1);

    // per-element state: thread tid (<128) owns batch element blockIdx*128 + tid
    const int bidx = blockIdx.x * 128 + tid;
    const bool owner = (tid < 128);
    float px = 0.f, py = 0.f, wxv = 0.f, wyv = 0.f;
    float msafe = -INFINITY, ssafe = 0.f, mreach = -INFINITY, sreach = 0.f;
    if (owner) {
        px = pos0[2 * bidx]; py = pos0[2 * bidx + 1];
        wxv = wind[2 * bidx]; wyv = wind[2 * bidx + 1];
    }
    const float ox0 = 1.75f, oy0 = 1.75f, r0c = 0.38f;
    const float ox1 = 1.75f, oy1 = 3.75f, r1c = 0.42f;
    const float ox2 = 3.75f, oy2 = 2.00f, r2c = 0.34f;

    // prologue: stage W1 -> buf0, w2 chunk0 -> buf1
    {
        float rr[32];
        ldgw1(rr, w1, tid);
        sts_pairs<2>(smw, BB_W, BB_W + BSZ_W, rr, tid);
        ldg32(rr, w2, 0, tid);
        sts_pairs<4>(smw, BB_W + 2 * BSZ_W, BB_W + 3 * BSZ_W, rr, tid);
    }
    __syncthreads();

    float cf[32][4];
#pragma unroll
    for (int j = 0; j < 32; ++j) { cf[j][0] = cf[j][1] = cf[j][2] = cf[j][3] = 0.f; }
    uint32_t bp = 0;
    float r[32];

#pragma unroll 1
    for (int t = 0; t < HOR; ++t) {
        // ---- obs -> A smem rows (k 0..15, bf16 hi/lo), element m = tid ----
        if (owner) {
            float o[16];
            o[0] = px * 0.1f; o[1] = py * 0.1f;
            o[2] = (4.0f - px) * 0.1f; o[3] = (3.0f - py) * 0.1f;
            float dx0 = px - ox0, dy0 = py - oy0;
            float dx1 = px - ox1, dy1 = py - oy1;
            float dx2 = px - ox2, dy2 = py - oy2;
            float d0 = sqrtf(dx0 * dx0 + dy0 * dy0 + 1e-9f);
            float d1 = sqrtf(dx1 * dx1 + dy1 * dy1 + 1e-9f);
            float d2 = sqrtf(dx2 * dx2 + dy2 * dy2 + 1e-9f);
            o[4] = -dx0 * 0.1f; o[5] = -dy0 * 0.1f;
            o[6] = -dx1 * 0.1f; o[7] = -dy1 * 0.1f;
            o[8] = -dx2 * 0.1f; o[9] = -dy2 * 0.1f;
            o[10] = d0 - r0c; o[11] = d1 - r1c; o[12] = d2 - r2c;
            o[13] = 0.f; o[14] = 0.f; o[15] = 0.f;
            const uint32_t mb = (uint32_t)tid * APW;
#pragma unroll
            for (int i = 0; i < 8; ++i) {
                uint32_t h = cvt2(o[2 * i + 1], o[2 * i]);
                uint32_t lo = cvt2(o[2 * i + 1] - bhi(h), o[2 * i] - blo(h));
                smw[mb + i] = h;
                smw[mb + A_LO_W + i] = lo;
            }
        }
        __syncthreads();

        // ---- L1 (chunk i=0, data0=W1 in buf[bp]); stage data2 = w2 c1 ----
        ldg32(r, w2, 32, tid);
        {
            uint32_t bh = BB_W + bp * 2 * BSZ_W, bl = bh + BSZ_W;
            mma_chunk<1>(cf, smw, AH0, AH1, AL0, AL1, bh, bl, g, tg);
            epi_h(cf, smem, smw, B1W, AH0, AH1, AL0, AL1, tg);
            __syncthreads();
            sts_pairs<4>(smw, bh, bl, r, tid);
            __syncthreads();
            bp ^= 1;
        }

        // ---- 16 chunks: L2 (cc 0..7) + L3 (cc 8..15) ----
#pragma unroll 1
        for (int cc = 0; cc < 16; ++cc) {
            const int nd = cc + 3;          // data index to stage
            const bool isw1 = (nd == 17);
            if (nd <= 8)       ldg32(r, w2, (nd - 1) * 32, tid);
            else if (nd <= 16) ldg32(r, w3, (nd - 9) * 32, tid);
            else if (isw1)     ldgw1(r, w1, tid);
            else               ldg32(r, w2, 0, tid);

            const uint32_t koff = (uint32_t)(cc & 7) * 16u;
            const uint32_t bh = BB_W + bp * 2 * BSZ_W, bl = bh + BSZ_W;
            mma_chunk<2>(cf, smw, AH0 + koff, AH1 + koff, AL0 + koff, AL1 + koff,
                         bh, bl, g, tg);
            __syncthreads();
            if (isw1) sts_pairs<2>(smw, bh, bl, r, tid);
            else      sts_pairs<4>(smw, bh, bl, r, tid);
            __syncthreads();
            bp ^= 1;
            if (cc == 7) epi_h(cf, smem, smw, B2W, AH0, AH1, AL0, AL1, tg);
        }

        // ---- layer-3 epilogue: actions = clip(relu(C+b3) @ wmu + bmu) ----
        {
            float p00 = 0.f, p01 = 0.f, p10 = 0.f, p11 = 0.f;
#pragma unroll
            for (int j = 0; j < 32; ++j) {
                const int n = 8 * j + 2 * tg;
                float2 bb = *reinterpret_cast<const float2*>(smem + B3W + n);
                float v0 = fmaxf(cf[j][0] + bb.x, 0.f), v1 = fmaxf(cf[j][1] + bb.y, 0.f);
                float v2 = fmaxf(cf[j][2] + bb.x, 0.f), v3 = fmaxf(cf[j][3] + bb.y, 0.f);
                float2 u0 = *reinterpret_cast<const float2*>(smem + WMUW + n);
                float2 u1 = *reinterpret_cast<const float2*>(smem + WMUW + 256 + n);
                p00 = fmaf(v0, u0.x, fmaf(v1, u0.y, p00));
                p01 = fmaf(v0, u1.x, fmaf(v1, u1.y, p01));
                p10 = fmaf(v2, u0.x, fmaf(v3, u0.y, p10));
                p11 = fmaf(v2, u1.x, fmaf(v3, u1.y, p11));
                cf[j][0] = cf[j][1] = cf[j][2] = cf[j][3] = 0.f;
            }
            p00 += __shfl_xor_sync(0xffffffffu, p00, 1);
            p00 += __shfl_xor_sync(0xffffffffu, p00, 2);
            p01 += __shfl_xor_sync(0xffffffffu, p01, 1);
            p01 += __shfl_xor_sync(0xffffffffu, p01, 2);
            p10 += __shfl_xor_sync(0xffffffffu, p10, 1);
            p10 += __shfl_xor_sync(0xffffffffu, p10, 2);
            p11 += __shfl_xor_sync(0xffffffffu, p11, 1);
            p11 += __shfl_xor_sync(0xffffffffu, p11, 2);
            if (tg == 0) {
                *reinterpret_cast<float2*>(smem + ACTW + 2 * m0) = make_float2(p00 + bmu0, p01 + bmu1);
                *reinterpret_cast<float2*>(smem + ACTW + 2 * m1) = make_float2(p10 + bmu0, p11 + bmu1);
            }
        }
        __syncthreads();

        // ---- dynamics + streaming STREL stats ----
        if (owner) {
            float2 a = *reinterpret_cast<const float2*>(smem + ACTW + 2 * tid);
            float ax = fminf(fmaxf(a.x, -1.0f), 1.0f);
            float ay = fminf(fmaxf(a.y, -1.0f), 1.0f);
            float vx = 2.0f * ax + wxv;
            float vy = 2.0f * ay + wyv;
#pragma unroll
            for (int s = 0; s < 4; ++s) {
                px = fminf(fmaxf(px + 0.0625f * vx, -4.0f), 10.0f);
                py = fminf(fmaxf(py + 0.0625f * vy, -4.0f), 10.0f);
            }
            float dx0 = px - ox0, dy0 = py - oy0;
            float dx1 = px - ox1, dy1 = py - oy1;
            float dx2 = px - ox2, dy2 = py - oy2;
            float c0 = sqrtf(dx0 * dx0 + dy0 * dy0 + 1e-9f) - r0c;
            float c1 = sqrtf(dx1 * dx1 + dy1 * dy1 + 1e-9f) - r1c;
            float c2 = sqrtf(dx2 * dx2 + dy2 * dy2 + 1e-9f) - r2c;
            float v0 = -50.0f * c0, v1 = -50.0f * c1, v2 = -50.0f * c2;
            float vm = fmaxf(v0, fmaxf(v1, v2));
            float lse = vm + logf(expf(v0 - vm) + expf(v1 - vm) + expf(v2 - vm));
            float safe = -lse / 50.0f;
            float vs = -8.0f * safe;
            if (vs > msafe) { ssafe = ssafe * expf(msafe - vs) + 1.0f; msafe = vs; }
            else            { ssafe += expf(vs - msafe); }
            float gdx = px - 4.0f, gdy = py - 3.0f;
            float gd = sqrtf(gdx * gdx + gdy * gdy + 1e-9f);
            float vr = 8.0f * (0.45f - gd);
            if (vr > mreach) { sreach = sreach * expf(mreach - vr) + 1.0f; mreach = vr; }
            else             { sreach += expf(vr - mreach); }
        }
        // top-of-loop obs write is ordered by the sync above
    }

    if (owner) {
        float rs = -(msafe + logf(ssafe)) * 0.125f;
        float rr = (mreach + logf(sreach)) * 0.125f;
        float u0 = -8.0f * rs, u1 = -8.0f * rr;
        float um = fmaxf(u0, u1);
        float rho = -(um + logf(expf(u0 - um) + expf(u1 - um))) * 0.125f;
        out[bidx] = rho;
    }
}

// ---------------- launch ----------------
extern "C" void kernel_launch(void* const* d_in, const int* in_sizes, int n_in,
                              void* d_out, int out_size) {
    const float* pos0 = (const float*)d_in[0];
    const float* wind = (const float*)d_in[1];
    const float* w1   = (const float*)d_in[2];
    const float* b1   = (const float*)d_in[3];
    const float* w2   = (const float*)d_in[4];
    const float* b2   = (const float*)d_in[5];
    const float* w3   = (const float*)d_in[6];
    const float* b3   = (const float*)d_in[7];
    const float* wmu  = (const float*)d_in[8];
    const float* bmu  = (const float*)d_in[9];
    float* out = (float*)d_out;

    cudaFuncSetAttribute(rollout_kernel,
                         cudaFuncAttributeMaxDynamicSharedMemorySize, SMEM_BYTES);

    int B = in_sizes[0] / 2;            // 32768
    int grid = B / 128;                 // 256
    rollout_kernel<<<grid, NTH, SMEM_BYTES>>>(pos0, wind, w1, b1, w2, b2,
                                              w3, b3, wmu, bmu, out);
}

// round 11
// speedup vs baseline: 3.0612x; 1.0369x over previous
#include <cuda_runtime.h>
#include <math.h>
#include <stdint.h>

#define NTH 512
#define HOR 64

// ---------------- smem word offsets ----------------
#define APW    132u                 // A row pitch (words); 132 mod 32 = 4 -> conflict-free
#define A_LO_W 16896u               // 128*132
#define BB_W   33792u               // B buffers start (4 x BSZ_W: {hi,lo} x 2)
#define BSZ_W  5120u                // 256 rows * 20 words
#define BPW    20u                  // B row pitch words
#define B1W    54272u
#define B2W    54528u
#define B3W    54784u
#define WMUW   55040u               // [2][256]
#define ACTW   55552u               // [2][128][2] floats = 512
#define SMEM_WORDS 56064u
#define SMEM_BYTES (SMEM_WORDS * 4u)

// ---------------- bf16 helpers ----------------
__device__ __forceinline__ uint32_t cvt2(float hi, float lo) {   // pack {hi,lo}, lo in bits[15:0]
    uint32_t r;
    asm("cvt.rn.bf16x2.f32 %0, %1, %2;" : "=r"(r) : "f"(hi), "f"(lo));
    return r;
}
__device__ __forceinline__ float blo(uint32_t p) { return __uint_as_float(p << 16); }
__device__ __forceinline__ float bhi(uint32_t p) { return __uint_as_float(p & 0xffff0000u); }

__device__ __forceinline__ uint32_t smem_u32(const void* p) {
    uint32_t a;
    asm("{ .reg .u64 t; cvta.to.shared.u64 t, %1; cvt.u32.u64 %0, t; }" : "=r"(a) : "l"(p));
    return a;
}

__device__ __forceinline__ void mma16816(float& c0, float& c1, float& c2, float& c3,
                                         uint32_t a0, uint32_t a1, uint32_t a2, uint32_t a3,
                                         uint32_t b0, uint32_t b1) {
    asm volatile("mma.sync.aligned.m16n8k16.row.col.f32.bf16.bf16.f32 "
        "{%0,%1,%2,%3}, {%4,%5,%6,%7}, {%8,%9}, {%0,%1,%2,%3};"
        : "+f"(c0), "+f"(c1), "+f"(c2), "+f"(c3)
        : "r"(a0), "r"(a1), "r"(a2), "r"(a3), "r"(b0), "r"(b1));
}
__device__ __forceinline__ void ldsm4(uint32_t& r0, uint32_t& r1, uint32_t& r2, uint32_t& r3,
                                      uint32_t addr) {
    asm volatile("ldmatrix.sync.aligned.m8n8.x4.shared.b16 {%0,%1,%2,%3}, [%4];"
        : "=r"(r0), "=r"(r1), "=r"(r2), "=r"(r3) : "r"(addr));
}

// ---------------- W staging (512 threads: n = tid&255, kh = tid>>8) ----------------
__device__ __forceinline__ void ldg16(float* r, const float* __restrict__ W, int k0, int n, int kh) {
#pragma unroll
    for (int k = 0; k < 16; ++k) r[k] = __ldg(W + (k0 + 16 * kh + k) * 256 + n);
}
__device__ __forceinline__ void sts16(uint32_t* __restrict__ smw, uint32_t hb, uint32_t lb,
                                      const float* r, int n, int kh) {
    const uint32_t base = (uint32_t)n * BPW + 8u * (uint32_t)kh;
#pragma unroll
    for (int h = 0; h < 2; ++h) {
        uint32_t hw[4], lw[4];
#pragma unroll
        for (int p = 0; p < 4; ++p) {
            float v0 = r[8 * h + 2 * p], v1 = r[8 * h + 2 * p + 1];
            uint32_t hh = cvt2(v1, v0);
            hw[p] = hh;
            lw[p] = cvt2(v1 - bhi(hh), v0 - blo(hh));
        }
        *reinterpret_cast<uint4*>(smw + hb + base + 4u * h) = make_uint4(hw[0], hw[1], hw[2], hw[3]);
        *reinterpret_cast<uint4*>(smw + lb + base + 4u * h) = make_uint4(lw[0], lw[1], lw[2], lw[3]);
    }
}
__device__ __forceinline__ void ldgw1h(float* r, const float* __restrict__ W, int n, int kh) {
#pragma unroll
    for (int k = 0; k < 8; ++k) {
        int kk = 8 * kh + k;
        r[k] = (kk < 13) ? __ldg(W + kk * 256 + n) : 0.0f;
    }
}
__device__ __forceinline__ void stsw1(uint32_t* __restrict__ smw, uint32_t hb, uint32_t lb,
                                      const float* r, int n, int kh) {
    const uint32_t base = (uint32_t)n * BPW + 4u * (uint32_t)kh;
    uint32_t hw[4], lw[4];
#pragma unroll
    for (int p = 0; p < 4; ++p) {
        float v0 = r[2 * p], v1 = r[2 * p + 1];
        uint32_t hh = cvt2(v1, v0);
        hw[p] = hh;
        lw[p] = cvt2(v1 - bhi(hh), v0 - blo(hh));
    }
    *reinterpret_cast<uint4*>(smw + hb + base) = make_uint4(hw[0], hw[1], hw[2], hw[3]);
    *reinterpret_cast<uint4*>(smw + lb + base) = make_uint4(lw[0], lw[1], lw[2], lw[3]);
}

// ---------------- MMA over one k-chunk: 16 j-tiles, NQ k16 steps ----------------
template <int NQ>
__device__ __forceinline__ void mma_chunk16(float (&c)[16][4],
                                            uint32_t aHiB, uint32_t aLoB,
                                            uint32_t bHiB, uint32_t bLoB) {
#pragma unroll
    for (int q = 0; q < NQ; ++q) {
        uint32_t ah0, ah1, ah2, ah3, al0, al1, al2, al3;
        ldsm4(ah0, ah1, ah2, ah3, aHiB + 32u * q);
        ldsm4(al0, al1, al2, al3, aLoB + 32u * q);
#pragma unroll
        for (int jp = 0; jp < 8; ++jp) {
            const uint32_t off = 1280u * (uint32_t)jp + 32u * q;  // 16 rows * 20 w * 4B
            uint32_t bh0, bh1, bh2, bh3, bl0, bl1, bl2, bl3;
            ldsm4(bh0, bh1, bh2, bh3, bHiB + off);
            ldsm4(bl0, bl1, bl2, bl3, bLoB + off);
            float* c0 = c[2 * jp];
            float* c1 = c[2 * jp + 1];
            mma16816(c0[0], c0[1], c0[2], c0[3], ah0, ah1, ah2, ah3, bh0, bh1);
            mma16816(c0[0], c0[1], c0[2], c0[3], ah0, ah1, ah2, ah3, bl0, bl1);
            mma16816(c0[0], c0[1], c0[2], c0[3], al0, al1, al2, al3, bh0, bh1);
            mma16816(c1[0], c1[1], c1[2], c1[3], ah0, ah1, ah2, ah3, bh2, bh3);
            mma16816(c1[0], c1[1], c1[2], c1[3], ah0, ah1, ah2, ah3, bl2, bl3);
            mma16816(c1[0], c1[1], c1[2], c1[3], al0, al1, al2, al3, bh2, bh3);
        }
    }
}

// h = relu(C + bias) -> A smem (bf16 hi/lo); zero C
__device__ __forceinline__ void epi_h(float (&c)[16][4], const float* __restrict__ smem,
                                      uint32_t* __restrict__ smw, uint32_t bW,
                                      int wm, int wn, int g, int tg) {
    const uint32_t r0w = (uint32_t)(16 * wm + g) * APW;
    const uint32_t r1w = r0w + 8u * APW;
#pragma unroll
    for (int j = 0; j < 16; ++j) {
        const int n = 128 * wn + 8 * j + 2 * tg;
        float2 bb = *reinterpret_cast<const float2*>(smem + bW + n);
        float v0 = fmaxf(c[j][0] + bb.x, 0.0f), v1 = fmaxf(c[j][1] + bb.y, 0.0f);
        float v2 = fmaxf(c[j][2] + bb.x, 0.0f), v3 = fmaxf(c[j][3] + bb.y, 0.0f);
        uint32_t h01 = cvt2(v1, v0);
        uint32_t l01 = cvt2(v1 - bhi(h01), v0 - blo(h01));
        uint32_t h23 = cvt2(v3, v2);
        uint32_t l23 = cvt2(v3 - bhi(h23), v2 - blo(h23));
        const uint32_t wof = (uint32_t)(n >> 1);
        smw[r0w + wof] = h01;
        smw[r1w + wof] = h23;
        smw[r0w + A_LO_W + wof] = l01;
        smw[r1w + A_LO_W + wof] = l23;
        c[j][0] = c[j][1] = c[j][2] = c[j][3] = 0.0f;
    }
}

// ---------------- main kernel ----------------
__global__ void __launch_bounds__(NTH, 1)
rollout_kernel(const float* __restrict__ pos0, const float* __restrict__ wind,
               const float* __restrict__ w1, const float* __restrict__ b1,
               const float* __restrict__ w2, const float* __restrict__ b2,
               const float* __restrict__ w3, const float* __restrict__ b3,
               const float* __restrict__ wmu, const float* __restrict__ bmu,
               float* __restrict__ out) {
    extern __shared__ float smem[];
    uint32_t* smw = reinterpret_cast<uint32_t*>(smem);
    const uint32_t sbase = smem_u32(smem);

    const int tid = threadIdx.x;
    const int w = tid >> 5, l = tid & 31;
    const int wm = w & 7, wn = w >> 3;
    const int g = l >> 2, tg = l & 3;

    // ldmatrix lane addresses (bytes)
    const int mlane = 16 * wm + 8 * ((l >> 3) & 1) + (l & 7);
    const uint32_t aHiB = sbase + 4u * ((uint32_t)mlane * APW + 4u * (uint32_t)(l >> 4));
    const uint32_t aLoB = aHiB + 4u * A_LO_W;
    const uint32_t bLaneW = ((uint32_t)(128 * wn + 8 * (l >> 4) + (l & 7))) * BPW
                          + 4u * (uint32_t)((l >> 3) & 1);

    // staging ids
    const int sn = tid & 255, skh = tid >> 8;

    // constants -> smem
    if (tid < 256) {
        smem[B1W + tid] = b1[tid];
        smem[B2W + tid] = b2[tid];
        smem[B3W + tid] = b3[tid];
        smem[WMUW + tid]        = wmu[tid * 2];
        smem[WMUW + 256 + tid]  = wmu[tid * 2 + 1];
    }
    const float bmu0 = __ldg(bmu), bmu1 = __ldg(bmu + 1);

    // per-element state: thread tid<128 owns batch element
    const int bidx = blockIdx.x * 128 + tid;
    const bool owner = (tid < 128);
    float px = 0.f, py = 0.f, wxv = 0.f, wyv = 0.f;
    float msafe = -INFINITY, ssafe = 0.f, mreach = -INFINITY, sreach = 0.f;
    if (owner) {
        px = pos0[2 * bidx]; py = pos0[2 * bidx + 1];
        wxv = wind[2 * bidx]; wyv = wind[2 * bidx + 1];
    }
    const float ox0 = 1.75f, oy0 = 1.75f, r0c = 0.38f;
    const float ox1 = 1.75f, oy1 = 3.75f, r1c = 0.42f;
    const float ox2 = 3.75f, oy2 = 2.00f, r2c = 0.34f;

    // prologue: item0 = W1 -> buf0, item1 = w2 c0 -> buf1
    {
        float rr[16];
        ldgw1h(rr, w1, sn, skh);
        stsw1(smw, BB_W, BB_W + BSZ_W, rr, sn, skh);
        ldg16(rr, w2, 0, sn, skh);
        sts16(smw, BB_W + 2u * BSZ_W, BB_W + 3u * BSZ_W, rr, sn, skh);
    }
    __syncthreads();

    float cf[16][4];
#pragma unroll
    for (int j = 0; j < 16; ++j) { cf[j][0] = cf[j][1] = cf[j][2] = cf[j][3] = 0.f; }
    uint32_t bp = 0;

#pragma unroll 1
    for (int t = 0; t < HOR; ++t) {
        // ---- obs -> A rows (k 0..15), owners = warps 0..3 ----
        if (owner) {
            float o[16];
            o[0] = px * 0.1f; o[1] = py * 0.1f;
            o[2] = (4.0f - px) * 0.1f; o[3] = (3.0f - py) * 0.1f;
            float dx0 = px - ox0, dy0 = py - oy0;
            float dx1 = px - ox1, dy1 = py - oy1;
            float dx2 = px - ox2, dy2 = py - oy2;
            float d0 = sqrtf(dx0 * dx0 + dy0 * dy0 + 1e-9f);
            float d1 = sqrtf(dx1 * dx1 + dy1 * dy1 + 1e-9f);
            float d2 = sqrtf(dx2 * dx2 + dy2 * dy2 + 1e-9f);
            o[4] = -dx0 * 0.1f; o[5] = -dy0 * 0.1f;
            o[6] = -dx1 * 0.1f; o[7] = -dy1 * 0.1f;
            o[8] = -dx2 * 0.1f; o[9] = -dy2 * 0.1f;
            o[10] = d0 - r0c; o[11] = d1 - r1c; o[12] = d2 - r2c;
            o[13] = 0.f; o[14] = 0.f; o[15] = 0.f;
            const uint32_t mb = (uint32_t)tid * APW;
#pragma unroll
            for (int i = 0; i < 8; ++i) {
                uint32_t h = cvt2(o[2 * i + 1], o[2 * i]);
                uint32_t lo = cvt2(o[2 * i + 1] - bhi(h), o[2 * i] - blo(h));
                smw[mb + i] = h;
                smw[mb + A_LO_W + i] = lo;
            }
        }
        __syncthreads();

        // ---- L1: consumes buf[bp] (W1); prefetch item2 = w2 c1 ----
        {
            float rr[16];
            ldg16(rr, w2, 32, sn, skh);
            const uint32_t bh = sbase + 4u * (BB_W + bp * 2u * BSZ_W + bLaneW);
            mma_chunk16<1>(cf, aHiB, aLoB, bh, bh + 4u * BSZ_W);
            __syncthreads();                                   // all warps done reading A(obs) + buf
            epi_h(cf, smem, smw, B1W, wm, wn, g, tg);          // h1 -> A
            sts16(smw, BB_W + bp * 2u * BSZ_W, BB_W + bp * 2u * BSZ_W + BSZ_W, rr, sn, skh);
            __syncthreads();
            bp ^= 1;
        }

        // ---- 16 chunks: L2 (cc 0..7) + L3 (cc 8..15) ----
#pragma unroll 1
        for (int cc = 0; cc < 16; ++cc) {
            float rr[16];
            const int nd = cc + 3;
            const bool isw1 = (nd == 17);
            if (nd <= 8)       ldg16(rr, w2, (nd - 1) * 32, sn, skh);
            else if (nd <= 16) ldg16(rr, w3, (nd - 9) * 32, sn, skh);
            else if (isw1)     ldgw1h(rr, w1, sn, skh);
            else               ldg16(rr, w2, 0, sn, skh);

            const uint32_t akoffB = 64u * (uint32_t)(cc & 7);
            const uint32_t bh = sbase + 4u * (BB_W + bp * 2u * BSZ_W + bLaneW);
            mma_chunk16<2>(cf, aHiB + akoffB, aLoB + akoffB, bh, bh + 4u * BSZ_W);
            __syncthreads();
            if (isw1) stsw1(smw, BB_W + bp * 2u * BSZ_W, BB_W + bp * 2u * BSZ_W + BSZ_W, rr, sn, skh);
            else      sts16(smw, BB_W + bp * 2u * BSZ_W, BB_W + bp * 2u * BSZ_W + BSZ_W, rr, sn, skh);
            __syncthreads();
            bp ^= 1;
            if (cc == 7) {
                epi_h(cf, smem, smw, B2W, wm, wn, g, tg);      // h2 -> A
                __syncthreads();
            }
        }

        // ---- actions: clip(relu(C+b3) @ wmu + bmu) with cross-warp-half reduce ----
        {
            float p00 = 0.f, p01 = 0.f, p10 = 0.f, p11 = 0.f;
#pragma unroll
            for (int j = 0; j < 16; ++j) {
                const int n = 128 * wn + 8 * j + 2 * tg;
                float2 bb = *reinterpret_cast<const float2*>(smem + B3W + n);
                float v0 = fmaxf(cf[j][0] + bb.x, 0.f), v1 = fmaxf(cf[j][1] + bb.y, 0.f);
                float v2 = fmaxf(cf[j][2] + bb.x, 0.f), v3 = fmaxf(cf[j][3] + bb.y, 0.f);
                float2 u0 = *reinterpret_cast<const float2*>(smem + WMUW + n);
                float2 u1 = *reinterpret_cast<const float2*>(smem + WMUW + 256 + n);
                p00 = fmaf(v0, u0.x, fmaf(v1, u0.y, p00));
                p01 = fmaf(v0, u1.x, fmaf(v1, u1.y, p01));
                p10 = fmaf(v2, u0.x, fmaf(v3, u0.y, p10));
                p11 = fmaf(v2, u1.x, fmaf(v3, u1.y, p11));
                cf[j][0] = cf[j][1] = cf[j][2] = cf[j][3] = 0.f;
            }
            p00 += __shfl_xor_sync(0xffffffffu, p00, 1);
            p00 += __shfl_xor_sync(0xffffffffu, p00, 2);
            p01 += __shfl_xor_sync(0xffffffffu, p01, 1);
            p01 += __shfl_xor_sync(0xffffffffu, p01, 2);
            p10 += __shfl_xor_sync(0xffffffffu, p10, 1);
            p10 += __shfl_xor_sync(0xffffffffu, p10, 2);
            p11 += __shfl_xor_sync(0xffffffffu, p11, 1);
            p11 += __shfl_xor_sync(0xffffffffu, p11, 2);
            if (tg == 0) {
                const int m0 = 16 * wm + g;
                *reinterpret_cast<float2*>(smem + ACTW + wn * 256 + 2 * m0) =
                    make_float2(p00, p01);
                *reinterpret_cast<float2*>(smem + ACTW + wn * 256 + 2 * (m0 + 8)) =
                    make_float2(p10, p11);
            }
        }
        __syncthreads();

        // ---- dynamics + streaming STREL stats ----
        if (owner) {
            float2 a0 = *reinterpret_cast<const float2*>(smem + ACTW + 2 * tid);
            float2 a1 = *reinterpret_cast<const float2*>(smem + ACTW + 256 + 2 * tid);
            float ax = fminf(fmaxf(a0.x + a1.x + bmu0, -1.0f), 1.0f);
            float ay = fminf(fmaxf(a0.y + a1.y + bmu1, -1.0f), 1.0f);
            float vx = 2.0f * ax + wxv;
            float vy = 2.0f * ay + wyv;
#pragma unroll
            for (int s = 0; s < 4; ++s) {
                px = fminf(fmaxf(px + 0.0625f * vx, -4.0f), 10.0f);
                py = fminf(fmaxf(py + 0.0625f * vy, -4.0f), 10.0f);
            }
            float dx0 = px - ox0, dy0 = py - oy0;
            float dx1 = px - ox1, dy1 = py - oy1;
            float dx2 = px - ox2, dy2 = py - oy2;
            float c0 = sqrtf(dx0 * dx0 + dy0 * dy0 + 1e-9f) - r0c;
            float c1 = sqrtf(dx1 * dx1 + dy1 * dy1 + 1e-9f) - r1c;
            float c2 = sqrtf(dx2 * dx2 + dy2 * dy2 + 1e-9f) - r2c;
            float v0 = -50.0f * c0, v1 = -50.0f * c1, v2 = -50.0f * c2;
            float vm = fmaxf(v0, fmaxf(v1, v2));
            float lse = vm + logf(expf(v0 - vm) + expf(v1 - vm) + expf(v2 - vm));
            float safe = -lse / 50.0f;
            float vs = -8.0f * safe;
            if (vs > msafe) { ssafe = ssafe * expf(msafe - vs) + 1.0f; msafe = vs; }
            else            { ssafe += expf(vs - msafe); }
            float gdx = px - 4.0f, gdy = py - 3.0f;
            float gd = sqrtf(gdx * gdx + gdy * gdy + 1e-9f);
            float vr = 8.0f * (0.45f - gd);
            if (vr > mreach) { sreach = sreach * expf(mreach - vr) + 1.0f; mreach = vr; }
            else             { sreach += expf(vr - mreach); }
        }
    }

    if (owner) {
        float rs = -(msafe + logf(ssafe)) * 0.125f;
        float rr = (mreach + logf(sreach)) * 0.125f;
        float u0 = -8.0f * rs, u1 = -8.0f * rr;
        float um = fmaxf(u0, u1);
        float rho = -(um + logf(expf(u0 - um) + expf(u1 - um))) * 0.125f;
        out[bidx] = rho;
    }
}

// ---------------- launch ----------------
extern "C" void kernel_launch(void* const* d_in, const int* in_sizes, int n_in,
                              void* d_out, int out_size) {
    const float* pos0 = (const float*)d_in[0];
    const float* wind = (const float*)d_in[1];
    const float* w1   = (const float*)d_in[2];
    const float* b1   = (const float*)d_in[3];
    const float* w2   = (const float*)d_in[4];
    const float* b2   = (const float*)d_in[5];
    const float* w3   = (const float*)d_in[6];
    const float* b3   = (const float*)d_in[7];
    const float* wmu  = (const float*)d_in[8];
    const float* bmu  = (const float*)d_in[9];
    float* out = (float*)d_out;

    cudaFuncSetAttribute(rollout_kernel,
                         cudaFuncAttributeMaxDynamicSharedMemorySize, SMEM_BYTES);

    int B = in_sizes[0] / 2;            // 32768
    int grid = B / 128;                 // 256
    rollout_kernel<<<grid, NTH, SMEM_BYTES>>>(pos0, wind, w1, b1, w2, b2,
                                              w3, b3, wmu, bmu, out);
}

// round 12
// speedup vs baseline: 3.0712x; 1.0033x over previous
#include <cuda_runtime.h>
#include <math.h>
#include <stdint.h>

#define NTH 512
#define HOR 64

// ---------------- smem word offsets ----------------
#define APW    132u                 // A row pitch (words); conflict-free
#define A_LO_W 16896u               // 128*132
#define BB_W   33792u               // B buffers: 2 pairs x (hi,lo) x BSZ_W
#define BSZ_W  5120u                // 256 rows * 20 words
#define BPW    20u                  // B row pitch words
#define B1W    54272u
#define B2W    54528u
#define B3W    54784u
#define WMUW   55040u               // [2][256]
#define ACTW   55552u               // [2][128][2] floats
#define SMEM_WORDS 56064u
#define SMEM_BYTES (SMEM_WORDS * 4u)

// item = 40KB = 10240 words: [hi 5120][lo 5120]; 17 items (w1, w2 c0..7, w3 c0..7)
#define ITEM_W 10240u
__device__ uint32_t g_wbuf[17 * 10240];

// ---------------- bf16 helpers ----------------
__device__ __forceinline__ uint32_t cvt2(float hi, float lo) {   // lo -> bits[15:0]
    uint32_t r;
    asm("cvt.rn.bf16x2.f32 %0, %1, %2;" : "=r"(r) : "f"(hi), "f"(lo));
    return r;
}
__device__ __forceinline__ float blo(uint32_t p) { return __uint_as_float(p << 16); }
__device__ __forceinline__ float bhi(uint32_t p) { return __uint_as_float(p & 0xffff0000u); }

__device__ __forceinline__ uint32_t smem_u32(const void* p) {
    uint32_t a;
    asm("{ .reg .u64 t; cvta.to.shared.u64 t, %1; cvt.u32.u64 %0, t; }" : "=r"(a) : "l"(p));
    return a;
}
__device__ __forceinline__ void mma16816(float& c0, float& c1, float& c2, float& c3,
                                         uint32_t a0, uint32_t a1, uint32_t a2, uint32_t a3,
                                         uint32_t b0, uint32_t b1) {
    asm volatile("mma.sync.aligned.m16n8k16.row.col.f32.bf16.bf16.f32 "
        "{%0,%1,%2,%3}, {%4,%5,%6,%7}, {%8,%9}, {%0,%1,%2,%3};"
        : "+f"(c0), "+f"(c1), "+f"(c2), "+f"(c3)
        : "r"(a0), "r"(a1), "r"(a2), "r"(a3), "r"(b0), "r"(b1));
}
__device__ __forceinline__ void ldsm4(uint32_t& r0, uint32_t& r1, uint32_t& r2, uint32_t& r3,
                                      uint32_t addr) {
    asm volatile("ldmatrix.sync.aligned.m8n8.x4.shared.b16 {%0,%1,%2,%3}, [%4];"
        : "=r"(r0), "=r"(r1), "=r"(r2), "=r"(r3) : "r"(addr));
}

// ---------------- prep kernel: fp32 W -> bf16 hi/lo smem-image ----------------
__global__ void prep_w(const float* __restrict__ w1, const float* __restrict__ w2,
                       const float* __restrict__ w3) {
    const int b = blockIdx.x;       // item 0..16
    const int n = threadIdx.x;      // 0..255
    uint32_t* hi = g_wbuf + (uint32_t)b * ITEM_W + (uint32_t)n * BPW;
    uint32_t* lo = hi + BSZ_W;
    float v[32];
    int nk;
    if (b == 0) {
        nk = 16;
#pragma unroll
        for (int k = 0; k < 16; ++k) v[k] = (k < 13) ? w1[k * 256 + n] : 0.0f;
    } else {
        nk = 32;
        const float* W = (b <= 8) ? w2 : w3;
        const int k0 = ((b - 1) & 7) * 32;
#pragma unroll
        for (int k = 0; k < 32; ++k) v[k] = W[(k0 + k) * 256 + n];
    }
    const int nw = nk >> 1;
    for (int wd = 0; wd < nw; ++wd) {
        float v0 = v[2 * wd], v1 = v[2 * wd + 1];
        uint32_t h = cvt2(v1, v0);
        hi[wd] = h;
        lo[wd] = cvt2(v1 - bhi(h), v0 - blo(h));
    }
    for (int wd = nw; wd < (int)BPW; ++wd) { hi[wd] = 0u; lo[wd] = 0u; }
}

// ---------------- cp.async staging: one 40KB item -> buffer pair nbp ----------------
__device__ __forceinline__ void stage_item(uint32_t sbase, uint32_t item, uint32_t nbp, int tid) {
    const uint32_t dst = sbase + 4u * (BB_W + nbp * 2u * BSZ_W) + (uint32_t)tid * 16u;
    const uint32_t* src = g_wbuf + item * ITEM_W + (uint32_t)tid * 4u;
#pragma unroll
    for (int i = 0; i < 5; ++i)
        asm volatile("cp.async.ca.shared.global [%0], [%1], 16;"
                     :: "r"(dst + 8192u * i), "l"(src + 2048u * i) : "memory");
    asm volatile("cp.async.commit_group;" ::: "memory");
}
#define CP_WAIT() asm volatile("cp.async.wait_group 0;" ::: "memory")

// ---------------- MMA over one k-chunk: 16 j-tiles, NQ k16 steps ----------------
template <int NQ>
__device__ __forceinline__ void mma_chunk16(float (&c)[16][4],
                                            uint32_t aHiB, uint32_t aLoB,
                                            uint32_t bHiB, uint32_t bLoB) {
#pragma unroll
    for (int q = 0; q < NQ; ++q) {
        uint32_t ah0, ah1, ah2, ah3, al0, al1, al2, al3;
        ldsm4(ah0, ah1, ah2, ah3, aHiB + 32u * q);
        ldsm4(al0, al1, al2, al3, aLoB + 32u * q);
#pragma unroll
        for (int jp = 0; jp < 8; ++jp) {
            const uint32_t off = 1280u * (uint32_t)jp + 32u * q;
            uint32_t bh0, bh1, bh2, bh3, bl0, bl1, bl2, bl3;
            ldsm4(bh0, bh1, bh2, bh3, bHiB + off);
            ldsm4(bl0, bl1, bl2, bl3, bLoB + off);
            float* c0 = c[2 * jp];
            float* c1 = c[2 * jp + 1];
            mma16816(c0[0], c0[1], c0[2], c0[3], ah0, ah1, ah2, ah3, bh0, bh1);
            mma16816(c0[0], c0[1], c0[2], c0[3], ah0, ah1, ah2, ah3, bl0, bl1);
            mma16816(c0[0], c0[1], c0[2], c0[3], al0, al1, al2, al3, bh0, bh1);
            mma16816(c1[0], c1[1], c1[2], c1[3], ah0, ah1, ah2, ah3, bh2, bh3);
            mma16816(c1[0], c1[1], c1[2], c1[3], ah0, ah1, ah2, ah3, bl2, bl3);
            mma16816(c1[0], c1[1], c1[2], c1[3], al0, al1, al2, al3, bh2, bh3);
        }
    }
}

// h = relu(C + bias) -> A smem (bf16 hi/lo); zero C
__device__ __forceinline__ void epi_h(float (&c)[16][4], const float* __restrict__ smem,
                                      uint32_t* __restrict__ smw, uint32_t bW,
                                      int wm, int wn, int g, int tg) {
    const uint32_t r0w = (uint32_t)(16 * wm + g) * APW;
    const uint32_t r1w = r0w + 8u * APW;
#pragma unroll
    for (int j = 0; j < 16; ++j) {
        const int n = 128 * wn + 8 * j + 2 * tg;
        float2 bb = *reinterpret_cast<const float2*>(smem + bW + n);
        float v0 = fmaxf(c[j][0] + bb.x, 0.0f), v1 = fmaxf(c[j][1] + bb.y, 0.0f);
        float v2 = fmaxf(c[j][2] + bb.x, 0.0f), v3 = fmaxf(c[j][3] + bb.y, 0.0f);
        uint32_t h01 = cvt2(v1, v0);
        uint32_t l01 = cvt2(v1 - bhi(h01), v0 - blo(h01));
        uint32_t h23 = cvt2(v3, v2);
        uint32_t l23 = cvt2(v3 - bhi(h23), v2 - blo(h23));
        const uint32_t wof = (uint32_t)(n >> 1);
        smw[r0w + wof] = h01;
        smw[r1w + wof] = h23;
        smw[r0w + A_LO_W + wof] = l01;
        smw[r1w + A_LO_W + wof] = l23;
        c[j][0] = c[j][1] = c[j][2] = c[j][3] = 0.0f;
    }
}

// ---------------- main kernel ----------------
__global__ void __launch_bounds__(NTH, 1)
rollout_kernel(const float* __restrict__ pos0, const float* __restrict__ wind,
               const float* __restrict__ b1, const float* __restrict__ b2,
               const float* __restrict__ b3,
               const float* __restrict__ wmu, const float* __restrict__ bmu,
               float* __restrict__ out) {
    extern __shared__ float smem[];
    uint32_t* smw = reinterpret_cast<uint32_t*>(smem);
    const uint32_t sbase = smem_u32(smem);

    const int tid = threadIdx.x;
    const int w = tid >> 5, l = tid & 31;
    const int wm = w & 7, wn = w >> 3;
    const int g = l >> 2, tg = l & 3;

    // ldmatrix lane addresses (bytes)
    const int mlane = 16 * wm + 8 * ((l >> 3) & 1) + (l & 7);
    const uint32_t aHiB = sbase + 4u * ((uint32_t)mlane * APW + 4u * (uint32_t)(l >> 4));
    const uint32_t aLoB = aHiB + 4u * A_LO_W;
    const uint32_t bLaneW = ((uint32_t)(128 * wn + 8 * (l >> 4) + (l & 7))) * BPW
                          + 4u * (uint32_t)((l >> 3) & 1);

    // constants -> smem
    if (tid < 256) {
        smem[B1W + tid] = b1[tid];
        smem[B2W + tid] = b2[tid];
        smem[B3W + tid] = b3[tid];
        smem[WMUW + tid]        = wmu[tid * 2];
        smem[WMUW + 256 + tid]  = wmu[tid * 2 + 1];
    }
    const float bmu0 = __ldg(bmu), bmu1 = __ldg(bmu + 1);

    // per-element state: thread tid<128 owns batch element
    const int bidx = blockIdx.x * 128 + tid;
    const bool owner = (tid < 128);
    float px = 0.f, py = 0.f, wxv = 0.f, wyv = 0.f;
    float msafe = -INFINITY, ssafe = 0.f, mreach = -INFINITY, sreach = 0.f;
    if (owner) {
        px = pos0[2 * bidx]; py = pos0[2 * bidx + 1];
        wxv = wind[2 * bidx]; wyv = wind[2 * bidx + 1];
    }
    const float ox0 = 1.75f, oy0 = 1.75f, r0c = 0.38f;
    const float ox1 = 1.75f, oy1 = 3.75f, r1c = 0.42f;
    const float ox2 = 3.75f, oy2 = 2.00f, r2c = 0.34f;

    // prologue: stage item0 (W1) -> buf0
    stage_item(sbase, 0u, 0u, tid);
    CP_WAIT();
    __syncthreads();

    float cf[16][4];
#pragma unroll
    for (int j = 0; j < 16; ++j) { cf[j][0] = cf[j][1] = cf[j][2] = cf[j][3] = 0.f; }
    uint32_t bp = 0;

#pragma unroll 1
    for (int t = 0; t < HOR; ++t) {
        // ---- obs -> A rows (k 0..15) ----
        if (owner) {
            float o[16];
            o[0] = px * 0.1f; o[1] = py * 0.1f;
            o[2] = (4.0f - px) * 0.1f; o[3] = (3.0f - py) * 0.1f;
            float dx0 = px - ox0, dy0 = py - oy0;
            float dx1 = px - ox1, dy1 = py - oy1;
            float dx2 = px - ox2, dy2 = py - oy2;
            float d0 = sqrtf(dx0 * dx0 + dy0 * dy0 + 1e-9f);
            float d1 = sqrtf(dx1 * dx1 + dy1 * dy1 + 1e-9f);
            float d2 = sqrtf(dx2 * dx2 + dy2 * dy2 + 1e-9f);
            o[4] = -dx0 * 0.1f; o[5] = -dy0 * 0.1f;
            o[6] = -dx1 * 0.1f; o[7] = -dy1 * 0.1f;
            o[8] = -dx2 * 0.1f; o[9] = -dy2 * 0.1f;
            o[10] = d0 - r0c; o[11] = d1 - r1c; o[12] = d2 - r2c;
            o[13] = 0.f; o[14] = 0.f; o[15] = 0.f;
            const uint32_t mb = (uint32_t)tid * APW;
#pragma unroll
            for (int i = 0; i < 8; ++i) {
                uint32_t h = cvt2(o[2 * i + 1], o[2 * i]);
                uint32_t lo = cvt2(o[2 * i + 1] - bhi(h), o[2 * i] - blo(h));
                smw[mb + i] = h;
                smw[mb + A_LO_W + i] = lo;
            }
        }
        __syncthreads();

        // ---- L1: consume buf[bp]=item0; stage item1 -> buf[bp^1] ----
        {
            stage_item(sbase, 1u, bp ^ 1u, tid);
            const uint32_t bh = sbase + 4u * (BB_W + bp * 2u * BSZ_W + bLaneW);
            mma_chunk16<1>(cf, aHiB, aLoB, bh, bh + 4u * BSZ_W);
            CP_WAIT();
            __syncthreads();
            epi_h(cf, smem, smw, B1W, wm, wn, g, tg);
            __syncthreads();
            bp ^= 1u;
        }

        // ---- 16 chunks: L2 (cc 0..7, items 1..8) + L3 (cc 8..15, items 9..16) ----
#pragma unroll 1
        for (int cc = 0; cc < 16; ++cc) {
            uint32_t nit = (uint32_t)(cc + 2);
            if (nit >= 17u) nit = 0u;                  // wrap: stage next step's W1
            stage_item(sbase, nit, bp ^ 1u, tid);
            const uint32_t akoffB = 64u * (uint32_t)(cc & 7);
            const uint32_t bh = sbase + 4u * (BB_W + bp * 2u * BSZ_W + bLaneW);
            mma_chunk16<2>(cf, aHiB + akoffB, aLoB + akoffB, bh, bh + 4u * BSZ_W);
            CP_WAIT();
            __syncthreads();
            if (cc == 7) {
                epi_h(cf, smem, smw, B2W, wm, wn, g, tg);
                __syncthreads();
            }
            bp ^= 1u;
        }

        // ---- actions: clip(relu(C+b3) @ wmu + bmu), cross-half reduce via smem ----
        {
            float p00 = 0.f, p01 = 0.f, p10 = 0.f, p11 = 0.f;
#pragma unroll
            for (int j = 0; j < 16; ++j) {
                const int n = 128 * wn + 8 * j + 2 * tg;
                float2 bb = *reinterpret_cast<const float2*>(smem + B3W + n);
                float v0 = fmaxf(cf[j][0] + bb.x, 0.f), v1 = fmaxf(cf[j][1] + bb.y, 0.f);
                float v2 = fmaxf(cf[j][2] + bb.x, 0.f), v3 = fmaxf(cf[j][3] + bb.y, 0.f);
                float2 u0 = *reinterpret_cast<const float2*>(smem + WMUW + n);
                float2 u1 = *reinterpret_cast<const float2*>(smem + WMUW + 256 + n);
                p00 = fmaf(v0, u0.x, fmaf(v1, u0.y, p00));
                p01 = fmaf(v0, u1.x, fmaf(v1, u1.y, p01));
                p10 = fmaf(v2, u0.x, fmaf(v3, u0.y, p10));
                p11 = fmaf(v2, u1.x, fmaf(v3, u1.y, p11));
                cf[j][0] = cf[j][1] = cf[j][2] = cf[j][3] = 0.f;
            }
            p00 += __shfl_xor_sync(0xffffffffu, p00, 1);
            p00 += __shfl_xor_sync(0xffffffffu, p00, 2);
            p01 += __shfl_xor_sync(0xffffffffu, p01, 1);
            p01 += __shfl_xor_sync(0xffffffffu, p01, 2);
            p10 += __shfl_xor_sync(0xffffffffu, p10, 1);
            p10 += __shfl_xor_sync(0xffffffffu, p10, 2);
            p11 += __shfl_xor_sync(0xffffffffu, p11, 1);
            p11 += __shfl_xor_sync(0xffffffffu, p11, 2);
            if (tg == 0) {
                const int m0 = 16 * wm + g;
                *reinterpret_cast<float2*>(smem + ACTW + wn * 256 + 2 * m0) =
                    make_float2(p00, p01);
                *reinterpret_cast<float2*>(smem + ACTW + wn * 256 + 2 * (m0 + 8)) =
                    make_float2(p10, p11);
            }
        }
        __syncthreads();

        // ---- dynamics + streaming STREL stats ----
        if (owner) {
            float2 a0 = *reinterpret_cast<const float2*>(smem + ACTW + 2 * tid);
            float2 a1 = *reinterpret_cast<const float2*>(smem + ACTW + 256 + 2 * tid);
            float ax = fminf(fmaxf(a0.x + a1.x + bmu0, -1.0f), 1.0f);
            float ay = fminf(fmaxf(a0.y + a1.y + bmu1, -1.0f), 1.0f);
            float vx = 2.0f * ax + wxv;
            float vy = 2.0f * ay + wyv;
#pragma unroll
            for (int s = 0; s < 4; ++s) {
                px = fminf(fmaxf(px + 0.0625f * vx, -4.0f), 10.0f);
                py = fminf(fmaxf(py + 0.0625f * vy, -4.0f), 10.0f);
            }
            float dx0 = px - ox0, dy0 = py - oy0;
            float dx1 = px - ox1, dy1 = py - oy1;
            float dx2 = px - ox2, dy2 = py - oy2;
            float c0 = sqrtf(dx0 * dx0 + dy0 * dy0 + 1e-9f) - r0c;
            float c1 = sqrtf(dx1 * dx1 + dy1 * dy1 + 1e-9f) - r1c;
            float c2 = sqrtf(dx2 * dx2 + dy2 * dy2 + 1e-9f) - r2c;
            float v0 = -50.0f * c0, v1 = -50.0f * c1, v2 = -50.0f * c2;
            float vm = fmaxf(v0, fmaxf(v1, v2));
            float lse = vm + logf(expf(v0 - vm) + expf(v1 - vm) + expf(v2 - vm));
            float safe = -lse / 50.0f;
            float vs = -8.0f * safe;
            if (vs > msafe) { ssafe = ssafe * expf(msafe - vs) + 1.0f; msafe = vs; }
            else            { ssafe += expf(vs - msafe); }
            float gdx = px - 4.0f, gdy = py - 3.0f;
            float gd = sqrtf(gdx * gdx + gdy * gdy + 1e-9f);
            float vr = 8.0f * (0.45f - gd);
            if (vr > mreach) { sreach = sreach * expf(mreach - vr) + 1.0f; mreach = vr; }
            else             { sreach += expf(vr - mreach); }
        }
    }

    if (owner) {
        float rs = -(msafe + logf(ssafe)) * 0.125f;
        float rr = (mreach + logf(sreach)) * 0.125f;
        float u0 = -8.0f * rs, u1 = -8.0f * rr;
        float um = fmaxf(u0, u1);
        float rho = -(um + logf(expf(u0 - um) + expf(u1 - um))) * 0.125f;
        out[bidx] = rho;
    }
}

// ---------------- launch ----------------
extern "C" void kernel_launch(void* const* d_in, const int* in_sizes, int n_in,
                              void* d_out, int out_size) {
    const float* pos0 = (const float*)d_in[0];
    const float* wind = (const float*)d_in[1];
    const float* w1   = (const float*)d_in[2];
    const float* b1   = (const float*)d_in[3];
    const float* w2   = (const float*)d_in[4];
    const float* b2   = (const float*)d_in[5];
    const float* w3   = (const float*)d_in[6];
    const float* b3   = (const float*)d_in[7];
    const float* wmu  = (const float*)d_in[8];
    const float* bmu  = (const float*)d_in[9];
    float* out = (float*)d_out;

    cudaFuncSetAttribute(rollout_kernel,
                         cudaFuncAttributeMaxDynamicSharedMemorySize, SMEM_BYTES);

    prep_w<<<17, 256>>>(w1, w2, w3);

    int B = in_sizes[0] / 2;            // 32768
    int grid = B / 128;                 // 256
    rollout_kernel<<<grid, NTH, SMEM_BYTES>>>(pos0, wind, b1, b2, b3,
                                              wmu, bmu, out);
}

// round 13
// speedup vs baseline: 4.7618x; 1.5505x over previous
#include <cuda_runtime.h>
#include <cuda_fp16.h>
#include <math.h>
#include <stdint.h>

#define NTH 512
#define HOR 64

// ---------------- smem word offsets ----------------
#define APW    132u                 // A row pitch (words); conflict-free
#define A_LO_W 16896u               // 128*132
#define BB_W   33792u               // B buffers: 2 x BSZ_W (fp16 single)
#define BSZ_W  5120u                // 256 rows * 20 words
#define BPW    20u                  // B row pitch words
#define B1W    44032u
#define B2W    44288u
#define B3W    44544u
#define WMUW   44800u               // [2][256]
#define ACTW   45312u               // [2][128][2] floats
#define SMEM_WORDS 45824u
#define SMEM_BYTES (SMEM_WORDS * 4u)

// item = 20KB = 5120 words (fp16 W image); 17 items (w1, w2 c0..7, w3 c0..7)
#define ITEM_W 5120u
__device__ uint32_t g_wbuf[17 * 5120];

// ---------------- fp16 helpers ----------------
__device__ __forceinline__ uint32_t pk16(float lo, float hi) {   // lo -> bits[15:0]
    __half2 h = __floats2half2_rn(lo, hi);
    return *reinterpret_cast<uint32_t*>(&h);
}
__device__ __forceinline__ float f16lo(uint32_t p) {
    __half2 h = *reinterpret_cast<__half2*>(&p);
    return __low2float(h);
}
__device__ __forceinline__ float f16hi(uint32_t p) {
    __half2 h = *reinterpret_cast<__half2*>(&p);
    return __high2float(h);
}

__device__ __forceinline__ uint32_t smem_u32(const void* p) {
    uint32_t a;
    asm("{ .reg .u64 t; cvta.to.shared.u64 t, %1; cvt.u32.u64 %0, t; }" : "=r"(a) : "l"(p));
    return a;
}
__device__ __forceinline__ void mma16816(float& c0, float& c1, float& c2, float& c3,
                                         uint32_t a0, uint32_t a1, uint32_t a2, uint32_t a3,
                                         uint32_t b0, uint32_t b1) {
    asm volatile("mma.sync.aligned.m16n8k16.row.col.f32.f16.f16.f32 "
        "{%0,%1,%2,%3}, {%4,%5,%6,%7}, {%8,%9}, {%0,%1,%2,%3};"
        : "+f"(c0), "+f"(c1), "+f"(c2), "+f"(c3)
        : "r"(a0), "r"(a1), "r"(a2), "r"(a3), "r"(b0), "r"(b1));
}
__device__ __forceinline__ void ldsm4(uint32_t& r0, uint32_t& r1, uint32_t& r2, uint32_t& r3,
                                      uint32_t addr) {
    asm volatile("ldmatrix.sync.aligned.m8n8.x4.shared.b16 {%0,%1,%2,%3}, [%4];"
        : "=r"(r0), "=r"(r1), "=r"(r2), "=r"(r3) : "r"(addr));
}

// ---------------- prep kernel: fp32 W -> fp16 smem-image ----------------
__global__ void prep_w(const float* __restrict__ w1, const float* __restrict__ w2,
                       const float* __restrict__ w3) {
    const int b = blockIdx.x;       // item 0..16
    const int n = threadIdx.x;      // 0..255
    uint32_t* dst = g_wbuf + (uint32_t)b * ITEM_W + (uint32_t)n * BPW;
    float v[32];
    int nk;
    if (b == 0) {
        nk = 16;
#pragma unroll
        for (int k = 0; k < 16; ++k) v[k] = (k < 13) ? w1[k * 256 + n] : 0.0f;
    } else {
        nk = 32;
        const float* W = (b <= 8) ? w2 : w3;
        const int k0 = ((b - 1) & 7) * 32;
#pragma unroll
        for (int k = 0; k < 32; ++k) v[k] = W[(k0 + k) * 256 + n];
    }
    const int nw = nk >> 1;
    for (int wd = 0; wd < nw; ++wd) dst[wd] = pk16(v[2 * wd], v[2 * wd + 1]);
    for (int wd = nw; wd < (int)BPW; ++wd) dst[wd] = 0u;
}

// ---------------- cp.async staging: one 20KB item -> buffer nbp ----------------
__device__ __forceinline__ void stage_item(uint32_t sbase, uint32_t item, uint32_t nbp, int tid) {
    const uint32_t dst = sbase + 4u * (BB_W + nbp * BSZ_W) + (uint32_t)tid * 16u;
    const uint32_t* src = g_wbuf + item * ITEM_W + (uint32_t)tid * 4u;
    asm volatile("cp.async.ca.shared.global [%0], [%1], 16;" :: "r"(dst), "l"(src) : "memory");
    asm volatile("cp.async.ca.shared.global [%0], [%1], 16;"
                 :: "r"(dst + 8192u), "l"(src + 2048u) : "memory");
    if (tid < 256)
        asm volatile("cp.async.ca.shared.global [%0], [%1], 16;"
                     :: "r"(dst + 16384u), "l"(src + 4096u) : "memory");
    asm volatile("cp.async.commit_group;" ::: "memory");
}
#define CP_WAIT() asm volatile("cp.async.wait_group 0;" ::: "memory")

// ---------------- MMA over one k-chunk: 16 j-tiles, NQ k16 steps ----------------
template <int NQ>
__device__ __forceinline__ void mma_chunk16(float (&c)[16][4],
                                            uint32_t aHiB, uint32_t aLoB, uint32_t bHiB) {
#pragma unroll
    for (int q = 0; q < NQ; ++q) {
        uint32_t ah0, ah1, ah2, ah3, al0, al1, al2, al3;
        ldsm4(ah0, ah1, ah2, ah3, aHiB + 32u * q);
        ldsm4(al0, al1, al2, al3, aLoB + 32u * q);
#pragma unroll
        for (int jp = 0; jp < 8; ++jp) {
            const uint32_t off = 1280u * (uint32_t)jp + 32u * q;
            uint32_t bh0, bh1, bh2, bh3;
            ldsm4(bh0, bh1, bh2, bh3, bHiB + off);
            float* c0 = c[2 * jp];
            float* c1 = c[2 * jp + 1];
            mma16816(c0[0], c0[1], c0[2], c0[3], ah0, ah1, ah2, ah3, bh0, bh1);
            mma16816(c0[0], c0[1], c0[2], c0[3], al0, al1, al2, al3, bh0, bh1);
            mma16816(c1[0], c1[1], c1[2], c1[3], ah0, ah1, ah2, ah3, bh2, bh3);
            mma16816(c1[0], c1[1], c1[2], c1[3], al0, al1, al2, al3, bh2, bh3);
        }
    }
}

// h = relu(C + bias) -> A smem (fp16 hi/lo); zero C
__device__ __forceinline__ void epi_h(float (&c)[16][4], const float* __restrict__ smem,
                                      uint32_t* __restrict__ smw, uint32_t bW,
                                      int wm, int wn, int g, int tg) {
    const uint32_t r0w = (uint32_t)(16 * wm + g) * APW;
    const uint32_t r1w = r0w + 8u * APW;
#pragma unroll
    for (int j = 0; j < 16; ++j) {
        const int n = 128 * wn + 8 * j + 2 * tg;
        float2 bb = *reinterpret_cast<const float2*>(smem + bW + n);
        float v0 = fmaxf(c[j][0] + bb.x, 0.0f), v1 = fmaxf(c[j][1] + bb.y, 0.0f);
        float v2 = fmaxf(c[j][2] + bb.x, 0.0f), v3 = fmaxf(c[j][3] + bb.y, 0.0f);
        uint32_t h01 = pk16(v0, v1);
        uint32_t l01 = pk16(v0 - f16lo(h01), v1 - f16hi(h01));
        uint32_t h23 = pk16(v2, v3);
        uint32_t l23 = pk16(v2 - f16lo(h23), v3 - f16hi(h23));
        const uint32_t wof = (uint32_t)(n >> 1);
        smw[r0w + wof] = h01;
        smw[r1w + wof] = h23;
        smw[r0w + A_LO_W + wof] = l01;
        smw[r1w + A_LO_W + wof] = l23;
        c[j][0] = c[j][1] = c[j][2] = c[j][3] = 0.0f;
    }
}

// ---------------- main kernel ----------------
__global__ void __launch_bounds__(NTH, 1)
rollout_kernel(const float* __restrict__ pos0, const float* __restrict__ wind,
               const float* __restrict__ b1, const float* __restrict__ b2,
               const float* __restrict__ b3,
               const float* __restrict__ wmu, const float* __restrict__ bmu,
               float* __restrict__ out) {
    extern __shared__ float smem[];
    uint32_t* smw = reinterpret_cast<uint32_t*>(smem);
    const uint32_t sbase = smem_u32(smem);

    const int tid = threadIdx.x;
    const int w = tid >> 5, l = tid & 31;
    const int wm = w & 7, wn = w >> 3;
    const int g = l >> 2, tg = l & 3;

    // ldmatrix lane addresses (bytes) — same mapping validated in R11/R12
    const int mlane = 16 * wm + 8 * ((l >> 3) & 1) + (l & 7);
    const uint32_t aHiB = sbase + 4u * ((uint32_t)mlane * APW + 4u * (uint32_t)(l >> 4));
    const uint32_t aLoB = aHiB + 4u * A_LO_W;
    const uint32_t bLaneW = ((uint32_t)(128 * wn + 8 * (l >> 4) + (l & 7))) * BPW
                          + 4u * (uint32_t)((l >> 3) & 1);

    // constants -> smem
    if (tid < 256) {
        smem[B1W + tid] = b1[tid];
        smem[B2W + tid] = b2[tid];
        smem[B3W + tid] = b3[tid];
        smem[WMUW + tid]        = wmu[tid * 2];
        smem[WMUW + 256 + tid]  = wmu[tid * 2 + 1];
    }
    const float bmu0 = __ldg(bmu), bmu1 = __ldg(bmu + 1);

    // per-element state
    const int bidx = blockIdx.x * 128 + tid;
    const bool owner = (tid < 128);
    float px = 0.f, py = 0.f, wxv = 0.f, wyv = 0.f;
    float msafe = -INFINITY, ssafe = 0.f, mreach = -INFINITY, sreach = 0.f;
    if (owner) {
        px = pos0[2 * bidx]; py = pos0[2 * bidx + 1];
        wxv = wind[2 * bidx]; wyv = wind[2 * bidx + 1];
    }
    const float ox0 = 1.75f, oy0 = 1.75f, r0c = 0.38f;
    const float ox1 = 1.75f, oy1 = 3.75f, r1c = 0.42f;
    const float ox2 = 3.75f, oy2 = 2.00f, r2c = 0.34f;

    // prologue: stage item0 (W1) -> buf0
    stage_item(sbase, 0u, 0u, tid);
    CP_WAIT();
    __syncthreads();

    float cf[16][4];
#pragma unroll
    for (int j = 0; j < 16; ++j) { cf[j][0] = cf[j][1] = cf[j][2] = cf[j][3] = 0.f; }
    uint32_t bp = 0;

#pragma unroll 1
    for (int t = 0; t < HOR; ++t) {
        // ---- obs -> A rows (k 0..15, fp16 hi/lo) ----
        if (owner) {
            float o[16];
            o[0] = px * 0.1f; o[1] = py * 0.1f;
            o[2] = (4.0f - px) * 0.1f; o[3] = (3.0f - py) * 0.1f;
            float dx0 = px - ox0, dy0 = py - oy0;
            float dx1 = px - ox1, dy1 = py - oy1;
            float dx2 = px - ox2, dy2 = py - oy2;
            float d0 = sqrtf(dx0 * dx0 + dy0 * dy0 + 1e-9f);
            float d1 = sqrtf(dx1 * dx1 + dy1 * dy1 + 1e-9f);
            float d2 = sqrtf(dx2 * dx2 + dy2 * dy2 + 1e-9f);
            o[4] = -dx0 * 0.1f; o[5] = -dy0 * 0.1f;
            o[6] = -dx1 * 0.1f; o[7] = -dy1 * 0.1f;
            o[8] = -dx2 * 0.1f; o[9] = -dy2 * 0.1f;
            o[10] = d0 - r0c; o[11] = d1 - r1c; o[12] = d2 - r2c;
            o[13] = 0.f; o[14] = 0.f; o[15] = 0.f;
            const uint32_t mb = (uint32_t)tid * APW;
#pragma unroll
            for (int i = 0; i < 8; ++i) {
                uint32_t h = pk16(o[2 * i], o[2 * i + 1]);
                uint32_t lo = pk16(o[2 * i] - f16lo(h), o[2 * i + 1] - f16hi(h));
                smw[mb + i] = h;
                smw[mb + A_LO_W + i] = lo;
            }
        }
        __syncthreads();

        // ---- L1: consume buf[bp]=item0; stage item1 -> buf[bp^1] ----
        {
            stage_item(sbase, 1u, bp ^ 1u, tid);
            const uint32_t bh = sbase + 4u * (BB_W + bp * BSZ_W + bLaneW);
            mma_chunk16<1>(cf, aHiB, aLoB, bh);
            CP_WAIT();
            __syncthreads();
            epi_h(cf, smem, smw, B1W, wm, wn, g, tg);
            __syncthreads();
            bp ^= 1u;
        }

        // ---- 16 chunks: L2 (cc 0..7, items 1..8) + L3 (cc 8..15, items 9..16) ----
#pragma unroll 1
        for (int cc = 0; cc < 16; ++cc) {
            uint32_t nit = (uint32_t)(cc + 2);
            if (nit >= 17u) nit = 0u;                  // wrap: next step's W1
            stage_item(sbase, nit, bp ^ 1u, tid);
            const uint32_t akoffB = 64u * (uint32_t)(cc & 7);
            const uint32_t bh = sbase + 4u * (BB_W + bp * BSZ_W + bLaneW);
            mma_chunk16<2>(cf, aHiB + akoffB, aLoB + akoffB, bh);
            CP_WAIT();
            __syncthreads();
            if (cc == 7) {
                epi_h(cf, smem, smw, B2W, wm, wn, g, tg);
                __syncthreads();
            }
            bp ^= 1u;
        }

        // ---- actions: clip(relu(C+b3) @ wmu + bmu), cross-half reduce ----
        {
            float p00 = 0.f, p01 = 0.f, p10 = 0.f, p11 = 0.f;
#pragma unroll
            for (int j = 0; j < 16; ++j) {
                const int n = 128 * wn + 8 * j + 2 * tg;
                float2 bb = *reinterpret_cast<const float2*>(smem + B3W + n);
                float v0 = fmaxf(cf[j][0] + bb.x, 0.f), v1 = fmaxf(cf[j][1] + bb.y, 0.f);
                float v2 = fmaxf(cf[j][2] + bb.x, 0.f), v3 = fmaxf(cf[j][3] + bb.y, 0.f);
                float2 u0 = *reinterpret_cast<const float2*>(smem + WMUW + n);
                float2 u1 = *reinterpret_cast<const float2*>(smem + WMUW + 256 + n);
                p00 = fmaf(v0, u0.x, fmaf(v1, u0.y, p00));
                p01 = fmaf(v0, u1.x, fmaf(v1, u1.y, p01));
                p10 = fmaf(v2, u0.x, fmaf(v3, u0.y, p10));
                p11 = fmaf(v2, u1.x, fmaf(v3, u1.y, p11));
                cf[j][0] = cf[j][1] = cf[j][2] = cf[j][3] = 0.f;
            }
            p00 += __shfl_xor_sync(0xffffffffu, p00, 1);
            p00 += __shfl_xor_sync(0xffffffffu, p00, 2);
            p01 += __shfl_xor_sync(0xffffffffu, p01, 1);
            p01 += __shfl_xor_sync(0xffffffffu, p01, 2);
            p10 += __shfl_xor_sync(0xffffffffu, p10, 1);
            p10 += __shfl_xor_sync(0xffffffffu, p10, 2);
            p11 += __shfl_xor_sync(0xffffffffu, p11, 1);
            p11 += __shfl_xor_sync(0xffffffffu, p11, 2);
            if (tg == 0) {
                const int m0 = 16 * wm + g;
                *reinterpret_cast<float2*>(smem + ACTW + wn * 256 + 2 * m0) =
                    make_float2(p00, p01);
                *reinterpret_cast<float2*>(smem + ACTW + wn * 256 + 2 * (m0 + 8)) =
                    make_float2(p10, p11);
            }
        }
        __syncthreads();

        // ---- dynamics + streaming STREL stats ----
        if (owner) {
            float2 a0 = *reinterpret_cast<const float2*>(smem + ACTW + 2 * tid);
            float2 a1 = *reinterpret_cast<const float2*>(smem + ACTW + 256 + 2 * tid);
            float ax = fminf(fmaxf(a0.x + a1.x + bmu0, -1.0f), 1.0f);
            float ay = fminf(fmaxf(a0.y + a1.y + bmu1, -1.0f), 1.0f);
            float vx = 2.0f * ax + wxv;
            float vy = 2.0f * ay + wyv;
#pragma unroll
            for (int s = 0; s < 4; ++s) {
                px = fminf(fmaxf(px + 0.0625f * vx, -4.0f), 10.0f);
                py = fminf(fmaxf(py + 0.0625f * vy, -4.0f), 10.0f);
            }
            float dx0 = px - ox0, dy0 = py - oy0;
            float dx1 = px - ox1, dy1 = py - oy1;
            float dx2 = px - ox2, dy2 = py - oy2;
            float c0 = sqrtf(dx0 * dx0 + dy0 * dy0 + 1e-9f) - r0c;
            float c1 = sqrtf(dx1 * dx1 + dy1 * dy1 + 1e-9f) - r1c;
            float c2 = sqrtf(dx2 * dx2 + dy2 * dy2 + 1e-9f) - r2c;
            float v0 = -50.0f * c0, v1 = -50.0f * c1, v2 = -50.0f * c2;
            float vm = fmaxf(v0, fmaxf(v1, v2));
            float lse = vm + logf(expf(v0 - vm) + expf(v1 - vm) + expf(v2 - vm));
            float safe = -lse / 50.0f;
            float vs = -8.0f * safe;
            if (vs > msafe) { ssafe = ssafe * expf(msafe - vs) + 1.0f; msafe = vs; }
            else            { ssafe += expf(vs - msafe); }
            float gdx = px - 4.0f, gdy = py - 3.0f;
            float gd = sqrtf(gdx * gdx + gdy * gdy + 1e-9f);
            float vr = 8.0f * (0.45f - gd);
            if (vr > mreach) { sreach = sreach * expf(mreach - vr) + 1.0f; mreach = vr; }
            else             { sreach += expf(vr - mreach); }
        }
    }

    if (owner) {
        float rs = -(msafe + logf(ssafe)) * 0.125f;
        float rr = (mreach + logf(sreach)) * 0.125f;
        float u0 = -8.0f * rs, u1 = -8.0f * rr;
        float um = fmaxf(u0, u1);
        float rho = -(um + logf(expf(u0 - um) + expf(u1 - um))) * 0.125f;
        out[bidx] = rho;
    }
}

// ---------------- launch ----------------
extern "C" void kernel_launch(void* const* d_in, const int* in_sizes, int n_in,
                              void* d_out, int out_size) {
    const float* pos0 = (const float*)d_in[0];
    const float* wind = (const float*)d_in[1];
    const float* w1   = (const float*)d_in[2];
    const float* b1   = (const float*)d_in[3];
    const float* w2   = (const float*)d_in[4];
    const float* b2   = (const float*)d_in[5];
    const float* w3   = (const float*)d_in[6];
    const float* b3   = (const float*)d_in[7];
    const float* wmu  = (const float*)d_in[8];
    const float* bmu  = (const float*)d_in[9];
    float* out = (float*)d_out;

    cudaFuncSetAttribute(rollout_kernel,
                         cudaFuncAttributeMaxDynamicSharedMemorySize, SMEM_BYTES);

    prep_w<<<17, 256>>>(w1, w2, w3);

    int B = in_sizes[0] / 2;            // 32768
    int grid = B / 128;                 // 256
    rollout_kernel<<<grid, NTH, SMEM_BYTES>>>(pos0, wind, b1, b2, b3,
                                              wmu, bmu, out);
}

// round 14
// speedup vs baseline: 4.8044x; 1.0089x over previous
#include <cuda_runtime.h>
#include <cuda_fp16.h>
#include <math.h>
#include <stdint.h>

#define NTH 256
#define HOR 64

// ---------------- smem word offsets (64-row tile) ----------------
#define APW    132u                 // A row pitch (words); conflict-free
#define A_LO_W 8448u                // 64*132
#define BB_W   16896u               // B buffers: 2 x BSZ_W (fp16)
#define BSZ_W  5120u                // 256 rows * 20 words
#define BPW    20u                  // B row pitch words
#define B1W    27136u
#define B2W    27392u
#define B3W    27648u
#define WMUW   27904u               // [2][256]
#define ACTW   28416u               // [2][64][2] floats
#define SMEM_WORDS 28672u
#define SMEM_BYTES (SMEM_WORDS * 4u)   // 114688 B -> 2 CTAs/SM

// item = 20KB = 5120 words (fp16 W image); 17 items (w1, w2 c0..7, w3 c0..7)
#define ITEM_W 5120u
__device__ uint32_t g_wbuf[17 * 5120];

// ---------------- fp16 helpers ----------------
__device__ __forceinline__ uint32_t pk16(float lo, float hi) {
    __half2 h = __floats2half2_rn(lo, hi);
    return *reinterpret_cast<uint32_t*>(&h);
}
__device__ __forceinline__ float f16lo(uint32_t p) {
    __half2 h = *reinterpret_cast<__half2*>(&p);
    return __low2float(h);
}
__device__ __forceinline__ float f16hi(uint32_t p) {
    __half2 h = *reinterpret_cast<__half2*>(&p);
    return __high2float(h);
}

__device__ __forceinline__ uint32_t smem_u32(const void* p) {
    uint32_t a;
    asm("{ .reg .u64 t; cvta.to.shared.u64 t, %1; cvt.u32.u64 %0, t; }" : "=r"(a) : "l"(p));
    return a;
}
__device__ __forceinline__ void mma16816(float& c0, float& c1, float& c2, float& c3,
                                         uint32_t a0, uint32_t a1, uint32_t a2, uint32_t a3,
                                         uint32_t b0, uint32_t b1) {
    asm volatile("mma.sync.aligned.m16n8k16.row.col.f32.f16.f16.f32 "
        "{%0,%1,%2,%3}, {%4,%5,%6,%7}, {%8,%9}, {%0,%1,%2,%3};"
        : "+f"(c0), "+f"(c1), "+f"(c2), "+f"(c3)
        : "r"(a0), "r"(a1), "r"(a2), "r"(a3), "r"(b0), "r"(b1));
}
__device__ __forceinline__ void ldsm4(uint32_t& r0, uint32_t& r1, uint32_t& r2, uint32_t& r3,
                                      uint32_t addr) {
    asm volatile("ldmatrix.sync.aligned.m8n8.x4.shared.b16 {%0,%1,%2,%3}, [%4];"
        : "=r"(r0), "=r"(r1), "=r"(r2), "=r"(r3) : "r"(addr));
}

// ---------------- prep kernel: fp32 W -> fp16 smem-image ----------------
__global__ void prep_w(const float* __restrict__ w1, const float* __restrict__ w2,
                       const float* __restrict__ w3) {
    const int b = blockIdx.x;       // item 0..16
    const int n = threadIdx.x;      // 0..255
    uint32_t* dst = g_wbuf + (uint32_t)b * ITEM_W + (uint32_t)n * BPW;
    float v[32];
    int nk;
    if (b == 0) {
        nk = 16;
#pragma unroll
        for (int k = 0; k < 16; ++k) v[k] = (k < 13) ? w1[k * 256 + n] : 0.0f;
    } else {
        nk = 32;
        const float* W = (b <= 8) ? w2 : w3;
        const int k0 = ((b - 1) & 7) * 32;
#pragma unroll
        for (int k = 0; k < 32; ++k) v[k] = W[(k0 + k) * 256 + n];
    }
    const int nw = nk >> 1;
    for (int wd = 0; wd < nw; ++wd) dst[wd] = pk16(v[2 * wd], v[2 * wd + 1]);
    for (int wd = nw; wd < (int)BPW; ++wd) dst[wd] = 0u;
}

// ---------------- cp.async: one 20KB item -> buffer nbp (256 threads x 5 x 16B) ----
__device__ __forceinline__ void stage_item(uint32_t sbase, uint32_t item, uint32_t nbp, int tid) {
    const uint32_t dst = sbase + 4u * (BB_W + nbp * BSZ_W) + (uint32_t)tid * 16u;
    const uint32_t* src = g_wbuf + item * ITEM_W + (uint32_t)tid * 4u;
#pragma unroll
    for (int i = 0; i < 5; ++i)
        asm volatile("cp.async.ca.shared.global [%0], [%1], 16;"
                     :: "r"(dst + 4096u * i), "l"(src + 1024u * i) : "memory");
    asm volatile("cp.async.commit_group;" ::: "memory");
}
#define CP_WAIT() asm volatile("cp.async.wait_group 0;" ::: "memory")

// ---------------- MMA over one k-chunk: 16 j-tiles, NQ k16 steps ----------------
template <int NQ>
__device__ __forceinline__ void mma_chunk16(float (&c)[16][4],
                                            uint32_t aHiB, uint32_t aLoB, uint32_t bHiB) {
#pragma unroll
    for (int q = 0; q < NQ; ++q) {
        uint32_t ah0, ah1, ah2, ah3, al0, al1, al2, al3;
        ldsm4(ah0, ah1, ah2, ah3, aHiB + 32u * q);
        ldsm4(al0, al1, al2, al3, aLoB + 32u * q);
#pragma unroll
        for (int jp = 0; jp < 8; ++jp) {
            const uint32_t off = 1280u * (uint32_t)jp + 32u * q;
            uint32_t bh0, bh1, bh2, bh3;
            ldsm4(bh0, bh1, bh2, bh3, bHiB + off);
            float* c0 = c[2 * jp];
            float* c1 = c[2 * jp + 1];
            mma16816(c0[0], c0[1], c0[2], c0[3], ah0, ah1, ah2, ah3, bh0, bh1);
            mma16816(c0[0], c0[1], c0[2], c0[3], al0, al1, al2, al3, bh0, bh1);
            mma16816(c1[0], c1[1], c1[2], c1[3], ah0, ah1, ah2, ah3, bh2, bh3);
            mma16816(c1[0], c1[1], c1[2], c1[3], al0, al1, al2, al3, bh2, bh3);
        }
    }
}

// h = relu(C + bias) -> A smem (fp16 hi/lo); zero C
__device__ __forceinline__ void epi_h(float (&c)[16][4], const float* __restrict__ smem,
                                      uint32_t* __restrict__ smw, uint32_t bW,
                                      int wm, int wn, int g, int tg) {
    const uint32_t r0w = (uint32_t)(16 * wm + g) * APW;
    const uint32_t r1w = r0w + 8u * APW;
#pragma unroll
    for (int j = 0; j < 16; ++j) {
        const int n = 128 * wn + 8 * j + 2 * tg;
        float2 bb = *reinterpret_cast<const float2*>(smem + bW + n);
        float v0 = fmaxf(c[j][0] + bb.x, 0.0f), v1 = fmaxf(c[j][1] + bb.y, 0.0f);
        float v2 = fmaxf(c[j][2] + bb.x, 0.0f), v3 = fmaxf(c[j][3] + bb.y, 0.0f);
        uint32_t h01 = pk16(v0, v1);
        uint32_t l01 = pk16(v0 - f16lo(h01), v1 - f16hi(h01));
        uint32_t h23 = pk16(v2, v3);
        uint32_t l23 = pk16(v2 - f16lo(h23), v3 - f16hi(h23));
        const uint32_t wof = (uint32_t)(n >> 1);
        smw[r0w + wof] = h01;
        smw[r1w + wof] = h23;
        smw[r0w + A_LO_W + wof] = l01;
        smw[r1w + A_LO_W + wof] = l23;
        c[j][0] = c[j][1] = c[j][2] = c[j][3] = 0.0f;
    }
}

// ---------------- main kernel ----------------
__global__ void __launch_bounds__(NTH, 2)
rollout_kernel(const float* __restrict__ pos0, const float* __restrict__ wind,
               const float* __restrict__ b1, const float* __restrict__ b2,
               const float* __restrict__ b3,
               const float* __restrict__ wmu, const float* __restrict__ bmu,
               float* __restrict__ out) {
    extern __shared__ float smem[];
    uint32_t* smw = reinterpret_cast<uint32_t*>(smem);
    const uint32_t sbase = smem_u32(smem);

    const int tid = threadIdx.x;
    const int w = tid >> 5, l = tid & 31;
    const int wm = w & 3, wn = w >> 2;      // 4 m-blocks x 2 n-halves
    const int g = l >> 2, tg = l & 3;

    // ldmatrix lane addresses (bytes) — mapping identical to R13 modulo wm range
    const int mlane = 16 * wm + 8 * ((l >> 3) & 1) + (l & 7);
    const uint32_t aHiB = sbase + 4u * ((uint32_t)mlane * APW + 4u * (uint32_t)(l >> 4));
    const uint32_t aLoB = aHiB + 4u * A_LO_W;
    const uint32_t bLaneW = ((uint32_t)(128 * wn + 8 * (l >> 4) + (l & 7))) * BPW
                          + 4u * (uint32_t)((l >> 3) & 1);

    // constants -> smem
    smem[B1W + tid] = b1[tid];
    smem[B2W + tid] = b2[tid];
    smem[B3W + tid] = b3[tid];
    smem[WMUW + tid]        = wmu[tid * 2];
    smem[WMUW + 256 + tid]  = wmu[tid * 2 + 1];
    const float bmu0 = __ldg(bmu), bmu1 = __ldg(bmu + 1);

    // per-element state: thread tid<64 owns batch element
    const int bidx = blockIdx.x * 64 + tid;
    const bool owner = (tid < 64);
    float px = 0.f, py = 0.f, wxv = 0.f, wyv = 0.f;
    float msafe = -INFINITY, ssafe = 0.f, mreach = -INFINITY, sreach = 0.f;
    if (owner) {
        px = pos0[2 * bidx]; py = pos0[2 * bidx + 1];
        wxv = wind[2 * bidx]; wyv = wind[2 * bidx + 1];
    }
    const float ox0 = 1.75f, oy0 = 1.75f, r0c = 0.38f;
    const float ox1 = 1.75f, oy1 = 3.75f, r1c = 0.42f;
    const float ox2 = 3.75f, oy2 = 2.00f, r2c = 0.34f;

    // prologue: stage item0 (W1) -> buf0
    stage_item(sbase, 0u, 0u, tid);
    CP_WAIT();
    __syncthreads();

    float cf[16][4];
#pragma unroll
    for (int j = 0; j < 16; ++j) { cf[j][0] = cf[j][1] = cf[j][2] = cf[j][3] = 0.f; }
    uint32_t bp = 0;

#pragma unroll 1
    for (int t = 0; t < HOR; ++t) {
        // ---- obs -> A rows (k 0..15, fp16 hi/lo) ----
        if (owner) {
            float o[16];
            o[0] = px * 0.1f; o[1] = py * 0.1f;
            o[2] = (4.0f - px) * 0.1f; o[3] = (3.0f - py) * 0.1f;
            float dx0 = px - ox0, dy0 = py - oy0;
            float dx1 = px - ox1, dy1 = py - oy1;
            float dx2 = px - ox2, dy2 = py - oy2;
            float d0 = sqrtf(dx0 * dx0 + dy0 * dy0 + 1e-9f);
            float d1 = sqrtf(dx1 * dx1 + dy1 * dy1 + 1e-9f);
            float d2 = sqrtf(dx2 * dx2 + dy2 * dy2 + 1e-9f);
            o[4] = -dx0 * 0.1f; o[5] = -dy0 * 0.1f;
            o[6] = -dx1 * 0.1f; o[7] = -dy1 * 0.1f;
            o[8] = -dx2 * 0.1f; o[9] = -dy2 * 0.1f;
            o[10] = d0 - r0c; o[11] = d1 - r1c; o[12] = d2 - r2c;
            o[13] = 0.f; o[14] = 0.f; o[15] = 0.f;
            const uint32_t mb = (uint32_t)tid * APW;
#pragma unroll
            for (int i = 0; i < 8; ++i) {
                uint32_t h = pk16(o[2 * i], o[2 * i + 1]);
                uint32_t lo = pk16(o[2 * i] - f16lo(h), o[2 * i + 1] - f16hi(h));
                smw[mb + i] = h;
                smw[mb + A_LO_W + i] = lo;
            }
        }
        __syncthreads();

        // ---- L1: consume buf[bp]=item0; stage item1 -> buf[bp^1] ----
        {
            stage_item(sbase, 1u, bp ^ 1u, tid);
            const uint32_t bh = sbase + 4u * (BB_W + bp * BSZ_W + bLaneW);
            mma_chunk16<1>(cf, aHiB, aLoB, bh);
            CP_WAIT();
            __syncthreads();
            epi_h(cf, smem, smw, B1W, wm, wn, g, tg);
            __syncthreads();
            bp ^= 1u;
        }

        // ---- 16 chunks: L2 (cc 0..7, items 1..8) + L3 (cc 8..15, items 9..16) ----
#pragma unroll 1
        for (int cc = 0; cc < 16; ++cc) {
            uint32_t nit = (uint32_t)(cc + 2);
            if (nit >= 17u) nit = 0u;                  // wrap: next step's W1
            stage_item(sbase, nit, bp ^ 1u, tid);
            const uint32_t akoffB = 64u * (uint32_t)(cc & 7);
            const uint32_t bh = sbase + 4u * (BB_W + bp * BSZ_W + bLaneW);
            mma_chunk16<2>(cf, aHiB + akoffB, aLoB + akoffB, bh);
            CP_WAIT();
            __syncthreads();
            if (cc == 7) {
                epi_h(cf, smem, smw, B2W, wm, wn, g, tg);
                __syncthreads();
            }
            bp ^= 1u;
        }

        // ---- actions: clip(relu(C+b3) @ wmu + bmu), cross-half reduce ----
        {
            float p00 = 0.f, p01 = 0.f, p10 = 0.f, p11 = 0.f;
#pragma unroll
            for (int j = 0; j < 16; ++j) {
                const int n = 128 * wn + 8 * j + 2 * tg;
                float2 bb = *reinterpret_cast<const float2*>(smem + B3W + n);
                float v0 = fmaxf(cf[j][0] + bb.x, 0.f), v1 = fmaxf(cf[j][1] + bb.y, 0.f);
                float v2 = fmaxf(cf[j][2] + bb.x, 0.f), v3 = fmaxf(cf[j][3] + bb.y, 0.f);
                float2 u0 = *reinterpret_cast<const float2*>(smem + WMUW + n);
                float2 u1 = *reinterpret_cast<const float2*>(smem + WMUW + 256 + n);
                p00 = fmaf(v0, u0.x, fmaf(v1, u0.y, p00));
                p01 = fmaf(v0, u1.x, fmaf(v1, u1.y, p01));
                p10 = fmaf(v2, u0.x, fmaf(v3, u0.y, p10));
                p11 = fmaf(v2, u1.x, fmaf(v3, u1.y, p11));
                cf[j][0] = cf[j][1] = cf[j][2] = cf[j][3] = 0.f;
            }
            p00 += __shfl_xor_sync(0xffffffffu, p00, 1);
            p00 += __shfl_xor_sync(0xffffffffu, p00, 2);
            p01 += __shfl_xor_sync(0xffffffffu, p01, 1);
            p01 += __shfl_xor_sync(0xffffffffu, p01, 2);
            p10 += __shfl_xor_sync(0xffffffffu, p10, 1);
            p10 += __shfl_xor_sync(0xffffffffu, p10, 2);
            p11 += __shfl_xor_sync(0xffffffffu, p11, 1);
            p11 += __shfl_xor_sync(0xffffffffu, p11, 2);
            if (tg == 0) {
                const int m0 = 16 * wm + g;
                *reinterpret_cast<float2*>(smem + ACTW + wn * 128 + 2 * m0) =
                    make_float2(p00, p01);
                *reinterpret_cast<float2*>(smem + ACTW + wn * 128 + 2 * (m0 + 8)) =
                    make_float2(p10, p11);
            }
        }
        __syncthreads();

        // ---- dynamics + streaming STREL stats ----
        if (owner) {
            float2 a0 = *reinterpret_cast<const float2*>(smem + ACTW + 2 * tid);
            float2 a1 = *reinterpret_cast<const float2*>(smem + ACTW + 128 + 2 * tid);
            float ax = fminf(fmaxf(a0.x + a1.x + bmu0, -1.0f), 1.0f);
            float ay = fminf(fmaxf(a0.y + a1.y + bmu1, -1.0f), 1.0f);
            float vx = 2.0f * ax + wxv;
            float vy = 2.0f * ay + wyv;
#pragma unroll
            for (int s = 0; s < 4; ++s) {
                px = fminf(fmaxf(px + 0.0625f * vx, -4.0f), 10.0f);
                py = fminf(fmaxf(py + 0.0625f * vy, -4.0f), 10.0f);
            }
            float dx0 = px - ox0, dy0 = py - oy0;
            float dx1 = px - ox1, dy1 = py - oy1;
            float dx2 = px - ox2, dy2 = py - oy2;
            float c0 = sqrtf(dx0 * dx0 + dy0 * dy0 + 1e-9f) - r0c;
            float c1 = sqrtf(dx1 * dx1 + dy1 * dy1 + 1e-9f) - r1c;
            float c2 = sqrtf(dx2 * dx2 + dy2 * dy2 + 1e-9f) - r2c;
            float v0 = -50.0f * c0, v1 = -50.0f * c1, v2 = -50.0f * c2;
            float vm = fmaxf(v0, fmaxf(v1, v2));
            float lse = vm + logf(expf(v0 - vm) + expf(v1 - vm) + expf(v2 - vm));
            float safe = -lse / 50.0f;
            float vs = -8.0f * safe;
            if (vs > msafe) { ssafe = ssafe * expf(msafe - vs) + 1.0f; msafe = vs; }
            else            { ssafe += expf(vs - msafe); }
            float gdx = px - 4.0f, gdy = py - 3.0f;
            float gd = sqrtf(gdx * gdx + gdy * gdy + 1e-9f);
            float vr = 8.0f * (0.45f - gd);
            if (vr > mreach) { sreach = sreach * expf(mreach - vr) + 1.0f; mreach = vr; }
            else             { sreach += expf(vr - mreach); }
        }
    }

    if (owner) {
        float rs = -(msafe + logf(ssafe)) * 0.125f;
        float rr = (mreach + logf(sreach)) * 0.125f;
        float u0 = -8.0f * rs, u1 = -8.0f * rr;
        float um = fmaxf(u0, u1);
        float rho = -(um + logf(expf(u0 - um) + expf(u1 - um))) * 0.125f;
        out[bidx] = rho;
    }
}

// ---------------- launch ----------------
extern "C" void kernel_launch(void* const* d_in, const int* in_sizes, int n_in,
                              void* d_out, int out_size) {
    const float* pos0 = (const float*)d_in[0];
    const float* wind = (const float*)d_in[1];
    const float* w1   = (const float*)d_in[2];
    const float* b1   = (const float*)d_in[3];
    const float* w2   = (const float*)d_in[4];
    const float* b2   = (const float*)d_in[5];
    const float* w3   = (const float*)d_in[6];
    const float* b3   = (const float*)d_in[7];
    const float* wmu  = (const float*)d_in[8];
    const float* bmu  = (const float*)d_in[9];
    float* out = (float*)d_out;

    cudaFuncSetAttribute(rollout_kernel,
                         cudaFuncAttributeMaxDynamicSharedMemorySize, SMEM_BYTES);

    prep_w<<<17, 256>>>(w1, w2, w3);

    int B = in_sizes[0] / 2;            // 32768
    int grid = B / 64;                  // 512
    rollout_kernel<<<grid, NTH, SMEM_BYTES>>>(pos0, wind, b1, b2, b3,
                                              wmu, bmu, out);
}

// round 15
// speedup vs baseline: 7.5144x; 1.5641x over previous
#include <cuda_runtime.h>
#include <cuda_fp16.h>
#include <math.h>
#include <stdint.h>

#define NTH 256
#define HOR 64

// ---------------- smem word offsets (64-row tile, fp16-hi A only) ----------------
#define APW    132u                 // A row pitch (words); conflict-free
#define BB_W   8448u                // B buffers: 2 x BSZ_W (fp16)
#define BSZ_W  5120u                // 256 rows * 20 words
#define BPW    20u                  // B row pitch words
#define B1W    18688u
#define B2W    18944u
#define B3W    19200u
#define WMUW   19456u               // [2][256]
#define ACTW   19968u               // [4][64][2] floats
#define SMEM_WORDS 20480u
#define SMEM_BYTES (SMEM_WORDS * 4u)   // 81920 B -> 2 CTAs/SM

// item = 20KB = 5120 words (fp16 W image); 17 items (w1, w2 c0..7, w3 c0..7)
#define ITEM_W 5120u
__device__ uint32_t g_wbuf[17 * 5120];

// ---------------- fp16 helpers ----------------
__device__ __forceinline__ uint32_t pk16(float lo, float hi) {
    __half2 h = __floats2half2_rn(lo, hi);
    return *reinterpret_cast<uint32_t*>(&h);
}

__device__ __forceinline__ uint32_t smem_u32(const void* p) {
    uint32_t a;
    asm("{ .reg .u64 t; cvta.to.shared.u64 t, %1; cvt.u32.u64 %0, t; }" : "=r"(a) : "l"(p));
    return a;
}
__device__ __forceinline__ void mma16816(float& c0, float& c1, float& c2, float& c3,
                                         uint32_t a0, uint32_t a1, uint32_t a2, uint32_t a3,
                                         uint32_t b0, uint32_t b1) {
    asm volatile("mma.sync.aligned.m16n8k16.row.col.f32.f16.f16.f32 "
        "{%0,%1,%2,%3}, {%4,%5,%6,%7}, {%8,%9}, {%0,%1,%2,%3};"
        : "+f"(c0), "+f"(c1), "+f"(c2), "+f"(c3)
        : "r"(a0), "r"(a1), "r"(a2), "r"(a3), "r"(b0), "r"(b1));
}
__device__ __forceinline__ void ldsm4(uint32_t& r0, uint32_t& r1, uint32_t& r2, uint32_t& r3,
                                      uint32_t addr) {
    asm volatile("ldmatrix.sync.aligned.m8n8.x4.shared.b16 {%0,%1,%2,%3}, [%4];"
        : "=r"(r0), "=r"(r1), "=r"(r2), "=r"(r3) : "r"(addr));
}

// ---------------- prep kernel: fp32 W -> fp16 smem-image ----------------
__global__ void prep_w(const float* __restrict__ w1, const float* __restrict__ w2,
                       const float* __restrict__ w3) {
    const int b = blockIdx.x;       // item 0..16
    const int n = threadIdx.x;      // 0..255
    uint32_t* dst = g_wbuf + (uint32_t)b * ITEM_W + (uint32_t)n * BPW;
    float v[32];
    int nk;
    if (b == 0) {
        nk = 16;
#pragma unroll
        for (int k = 0; k < 16; ++k) v[k] = (k < 13) ? w1[k * 256 + n] : 0.0f;
    } else {
        nk = 32;
        const float* W = (b <= 8) ? w2 : w3;
        const int k0 = ((b - 1) & 7) * 32;
#pragma unroll
        for (int k = 0; k < 32; ++k) v[k] = W[(k0 + k) * 256 + n];
    }
    const int nw = nk >> 1;
    for (int wd = 0; wd < nw; ++wd) dst[wd] = pk16(v[2 * wd], v[2 * wd + 1]);
    for (int wd = nw; wd < (int)BPW; ++wd) dst[wd] = 0u;
}

// ---------------- cp.async: one 20KB item -> buffer nbp (256 threads x 5 x 16B) ----
__device__ __forceinline__ void stage_item(uint32_t sbase, uint32_t item, uint32_t nbp, int tid) {
    const uint32_t dst = sbase + 4u * (BB_W + nbp * BSZ_W) + (uint32_t)tid * 16u;
    const uint32_t* src = g_wbuf + item * ITEM_W + (uint32_t)tid * 4u;
#pragma unroll
    for (int i = 0; i < 5; ++i)
        asm volatile("cp.async.ca.shared.global [%0], [%1], 16;"
                     :: "r"(dst + 4096u * i), "l"(src + 1024u * i) : "memory");
    asm volatile("cp.async.commit_group;" ::: "memory");
}
#define CP_WAIT() asm volatile("cp.async.wait_group 0;" ::: "memory")

// ---------------- MMA over one k-chunk: warp tile m32 x n64, NQ k16 steps ----------
// c[p][j][4]: p = m-block (rows 32wm+16p), j = n8 tile (cols 64wn+8j)
template <int NQ>
__device__ __forceinline__ void mma_chunk(float (&c)[2][8][4],
                                          uint32_t aB, uint32_t bB) {
#pragma unroll
    for (int q = 0; q < NQ; ++q) {
        uint32_t a00, a01, a02, a03, a10, a11, a12, a13;
        ldsm4(a00, a01, a02, a03, aB + 32u * q);            // m-block p=0
        ldsm4(a10, a11, a12, a13, aB + 8448u + 32u * q);    // p=1 (+16 rows * 132w * 4B)
#pragma unroll
        for (int jp = 0; jp < 4; ++jp) {
            const uint32_t off = 1280u * (uint32_t)jp + 32u * q;
            uint32_t b0, b1, b2, b3;
            ldsm4(b0, b1, b2, b3, bB + off);
            mma16816(c[0][2*jp][0],   c[0][2*jp][1],   c[0][2*jp][2],   c[0][2*jp][3],
                     a00, a01, a02, a03, b0, b1);
            mma16816(c[0][2*jp+1][0], c[0][2*jp+1][1], c[0][2*jp+1][2], c[0][2*jp+1][3],
                     a00, a01, a02, a03, b2, b3);
            mma16816(c[1][2*jp][0],   c[1][2*jp][1],   c[1][2*jp][2],   c[1][2*jp][3],
                     a10, a11, a12, a13, b0, b1);
            mma16816(c[1][2*jp+1][0], c[1][2*jp+1][1], c[1][2*jp+1][2], c[1][2*jp+1][3],
                     a10, a11, a12, a13, b2, b3);
        }
    }
}

__device__ __forceinline__ void zero_c(float (&c)[2][8][4]) {
#pragma unroll
    for (int p = 0; p < 2; ++p)
#pragma unroll
        for (int j = 0; j < 8; ++j)
#pragma unroll
            for (int q = 0; q < 4; ++q) c[p][j][q] = 0.0f;
}

// h = relu(C + bias) -> A smem (fp16 hi only); zero C
__device__ __forceinline__ void epi_h(float (&c)[2][8][4], const float* __restrict__ smem,
                                      uint32_t* __restrict__ smw, uint32_t bW,
                                      int wm, int wn, int g, int tg) {
#pragma unroll
    for (int p = 0; p < 2; ++p) {
        const uint32_t r0w = (uint32_t)(32 * wm + 16 * p + g) * APW;
        const uint32_t r1w = r0w + 8u * APW;
#pragma unroll
        for (int j = 0; j < 8; ++j) {
            const int n = 64 * wn + 8 * j + 2 * tg;
            float2 bb = *reinterpret_cast<const float2*>(smem + bW + n);
            float v0 = fmaxf(c[p][j][0] + bb.x, 0.0f), v1 = fmaxf(c[p][j][1] + bb.y, 0.0f);
            float v2 = fmaxf(c[p][j][2] + bb.x, 0.0f), v3 = fmaxf(c[p][j][3] + bb.y, 0.0f);
            const uint32_t wof = (uint32_t)(n >> 1);
            smw[r0w + wof] = pk16(v0, v1);
            smw[r1w + wof] = pk16(v2, v3);
            c[p][j][0] = c[p][j][1] = c[p][j][2] = c[p][j][3] = 0.0f;
        }
    }
}

// ---------------- main kernel ----------------
__global__ void __launch_bounds__(NTH, 2)
rollout_kernel(const float* __restrict__ pos0, const float* __restrict__ wind,
               const float* __restrict__ b1, const float* __restrict__ b2,
               const float* __restrict__ b3,
               const float* __restrict__ wmu, const float* __restrict__ bmu,
               float* __restrict__ out) {
    extern __shared__ float smem[];
    uint32_t* smw = reinterpret_cast<uint32_t*>(smem);
    const uint32_t sbase = smem_u32(smem);

    const int tid = threadIdx.x;
    const int w = tid >> 5, l = tid & 31;
    const int wm = w & 1, wn = w >> 1;      // 2 m-blocks x 4 n-quarters
    const int g = l >> 2, tg = l & 3;

    // ldmatrix lane addresses (bytes)
    const int mlane = 32 * wm + 8 * ((l >> 3) & 1) + (l & 7);
    const uint32_t aB = sbase + 4u * ((uint32_t)mlane * APW + 4u * (uint32_t)(l >> 4));
    const uint32_t bLaneW = ((uint32_t)(64 * wn + 8 * (l >> 4) + (l & 7))) * BPW
                          + 4u * (uint32_t)((l >> 3) & 1);

    // constants -> smem
    smem[B1W + tid] = b1[tid];
    smem[B2W + tid] = b2[tid];
    smem[B3W + tid] = b3[tid];
    smem[WMUW + tid]        = wmu[tid * 2];
    smem[WMUW + 256 + tid]  = wmu[tid * 2 + 1];
    const float bmu0 = __ldg(bmu), bmu1 = __ldg(bmu + 1);

    // per-element state: thread tid<64 owns batch element
    const int bidx = blockIdx.x * 64 + tid;
    const bool owner = (tid < 64);
    float px = 0.f, py = 0.f, wxv = 0.f, wyv = 0.f;
    float msafe = -INFINITY, ssafe = 0.f, mreach = -INFINITY, sreach = 0.f;
    if (owner) {
        px = pos0[2 * bidx]; py = pos0[2 * bidx + 1];
        wxv = wind[2 * bidx]; wyv = wind[2 * bidx + 1];
    }
    const float ox0 = 1.75f, oy0 = 1.75f, r0c = 0.38f;
    const float ox1 = 1.75f, oy1 = 3.75f, r1c = 0.42f;
    const float ox2 = 3.75f, oy2 = 2.00f, r2c = 0.34f;

    // prologue: stage item0 (W1) -> buf0
    stage_item(sbase, 0u, 0u, tid);
    CP_WAIT();
    __syncthreads();

    float cf[2][8][4];
    zero_c(cf);
    uint32_t bp = 0;

#pragma unroll 1
    for (int t = 0; t < HOR; ++t) {
        // ---- obs -> A rows (k 0..15, fp16) ----
        if (owner) {
            float o[16];
            o[0] = px * 0.1f; o[1] = py * 0.1f;
            o[2] = (4.0f - px) * 0.1f; o[3] = (3.0f - py) * 0.1f;
            float dx0 = px - ox0, dy0 = py - oy0;
            float dx1 = px - ox1, dy1 = py - oy1;
            float dx2 = px - ox2, dy2 = py - oy2;
            float d0 = sqrtf(dx0 * dx0 + dy0 * dy0 + 1e-9f);
            float d1 = sqrtf(dx1 * dx1 + dy1 * dy1 + 1e-9f);
            float d2 = sqrtf(dx2 * dx2 + dy2 * dy2 + 1e-9f);
            o[4] = -dx0 * 0.1f; o[5] = -dy0 * 0.1f;
            o[6] = -dx1 * 0.1f; o[7] = -dy1 * 0.1f;
            o[8] = -dx2 * 0.1f; o[9] = -dy2 * 0.1f;
            o[10] = d0 - r0c; o[11] = d1 - r1c; o[12] = d2 - r2c;
            o[13] = 0.f; o[14] = 0.f; o[15] = 0.f;
            const uint32_t mb = (uint32_t)tid * APW;
#pragma unroll
            for (int i = 0; i < 8; ++i) smw[mb + i] = pk16(o[2 * i], o[2 * i + 1]);
        }
        __syncthreads();

        // ---- L1: consume buf[bp]=item0; stage item1 -> buf[bp^1] ----
        {
            stage_item(sbase, 1u, bp ^ 1u, tid);
            const uint32_t bh = sbase + 4u * (BB_W + bp * BSZ_W + bLaneW);
            mma_chunk<1>(cf, aB, bh);
            CP_WAIT();
            __syncthreads();
            epi_h(cf, smem, smw, B1W, wm, wn, g, tg);
            __syncthreads();
            bp ^= 1u;
        }

        // ---- 16 chunks: L2 (cc 0..7, items 1..8) + L3 (cc 8..15, items 9..16) ----
#pragma unroll 1
        for (int cc = 0; cc < 16; ++cc) {
            uint32_t nit = (uint32_t)(cc + 2);
            if (nit >= 17u) nit = 0u;                  // wrap: next step's W1
            stage_item(sbase, nit, bp ^ 1u, tid);
            const uint32_t akoffB = 64u * (uint32_t)(cc & 7);
            const uint32_t bh = sbase + 4u * (BB_W + bp * BSZ_W + bLaneW);
            mma_chunk<2>(cf, aB + akoffB, bh);
            CP_WAIT();
            __syncthreads();
            if (cc == 7) {
                epi_h(cf, smem, smw, B2W, wm, wn, g, tg);
                __syncthreads();
            }
            bp ^= 1u;
        }

        // ---- actions: clip(relu(C+b3) @ wmu + bmu), reduce over 4 n-quarters ----
        {
#pragma unroll
            for (int p = 0; p < 2; ++p) {
                float p00 = 0.f, p01 = 0.f, p10 = 0.f, p11 = 0.f;
#pragma unroll
                for (int j = 0; j < 8; ++j) {
                    const int n = 64 * wn + 8 * j + 2 * tg;
                    float2 bb = *reinterpret_cast<const float2*>(smem + B3W + n);
                    float v0 = fmaxf(cf[p][j][0] + bb.x, 0.f), v1 = fmaxf(cf[p][j][1] + bb.y, 0.f);
                    float v2 = fmaxf(cf[p][j][2] + bb.x, 0.f), v3 = fmaxf(cf[p][j][3] + bb.y, 0.f);
                    float2 u0 = *reinterpret_cast<const float2*>(smem + WMUW + n);
                    float2 u1 = *reinterpret_cast<const float2*>(smem + WMUW + 256 + n);
                    p00 = fmaf(v0, u0.x, fmaf(v1, u0.y, p00));
                    p01 = fmaf(v0, u1.x, fmaf(v1, u1.y, p01));
                    p10 = fmaf(v2, u0.x, fmaf(v3, u0.y, p10));
                    p11 = fmaf(v2, u1.x, fmaf(v3, u1.y, p11));
                    cf[p][j][0] = cf[p][j][1] = cf[p][j][2] = cf[p][j][3] = 0.f;
                }
                p00 += __shfl_xor_sync(0xffffffffu, p00, 1);
                p00 += __shfl_xor_sync(0xffffffffu, p00, 2);
                p01 += __shfl_xor_sync(0xffffffffu, p01, 1);
                p01 += __shfl_xor_sync(0xffffffffu, p01, 2);
                p10 += __shfl_xor_sync(0xffffffffu, p10, 1);
                p10 += __shfl_xor_sync(0xffffffffu, p10, 2);
                p11 += __shfl_xor_sync(0xffffffffu, p11, 1);
                p11 += __shfl_xor_sync(0xffffffffu, p11, 2);
                if (tg == 0) {
                    const int m0 = 32 * wm + 16 * p + g;
                    *reinterpret_cast<float2*>(smem + ACTW + wn * 128 + 2 * m0) =
                        make_float2(p00, p01);
                    *reinterpret_cast<float2*>(smem + ACTW + wn * 128 + 2 * (m0 + 8)) =
                        make_float2(p10, p11);
                }
            }
        }
        __syncthreads();

        // ---- dynamics + streaming STREL stats ----
        if (owner) {
            float2 a0 = *reinterpret_cast<const float2*>(smem + ACTW + 2 * tid);
            float2 a1 = *reinterpret_cast<const float2*>(smem + ACTW + 128 + 2 * tid);
            float2 a2 = *reinterpret_cast<const float2*>(smem + ACTW + 256 + 2 * tid);
            float2 a3 = *reinterpret_cast<const float2*>(smem + ACTW + 384 + 2 * tid);
            float ax = fminf(fmaxf(a0.x + a1.x + a2.x + a3.x + bmu0, -1.0f), 1.0f);
            float ay = fminf(fmaxf(a0.y + a1.y + a2.y + a3.y + bmu1, -1.0f), 1.0f);
            float vx = 2.0f * ax + wxv;
            float vy = 2.0f * ay + wyv;
#pragma unroll
            for (int s = 0; s < 4; ++s) {
                px = fminf(fmaxf(px + 0.0625f * vx, -4.0f), 10.0f);
                py = fminf(fmaxf(py + 0.0625f * vy, -4.0f), 10.0f);
            }
            float dx0 = px - ox0, dy0 = py - oy0;
            float dx1 = px - ox1, dy1 = py - oy1;
            float dx2 = px - ox2, dy2 = py - oy2;
            float c0 = sqrtf(dx0 * dx0 + dy0 * dy0 + 1e-9f) - r0c;
            float c1 = sqrtf(dx1 * dx1 + dy1 * dy1 + 1e-9f) - r1c;
            float c2 = sqrtf(dx2 * dx2 + dy2 * dy2 + 1e-9f) - r2c;
            float v0 = -50.0f * c0, v1 = -50.0f * c1, v2 = -50.0f * c2;
            float vm = fmaxf(v0, fmaxf(v1, v2));
            float lse = vm + logf(expf(v0 - vm) + expf(v1 - vm) + expf(v2 - vm));
            float safe = -lse / 50.0f;
            float vs = -8.0f * safe;
            if (vs > msafe) { ssafe = ssafe * expf(msafe - vs) + 1.0f; msafe = vs; }
            else            { ssafe += expf(vs - msafe); }
            float gdx = px - 4.0f, gdy = py - 3.0f;
            float gd = sqrtf(gdx * gdx + gdy * gdy + 1e-9f);
            float vr = 8.0f * (0.45f - gd);
            if (vr > mreach) { sreach = sreach * expf(mreach - vr) + 1.0f; mreach = vr; }
            else             { sreach += expf(vr - mreach); }
        }
    }

    if (owner) {
        float rs = -(msafe + logf(ssafe)) * 0.125f;
        float rr = (mreach + logf(sreach)) * 0.125f;
        float u0 = -8.0f * rs, u1 = -8.0f * rr;
        float um = fmaxf(u0, u1);
        float rho = -(um + logf(expf(u0 - um) + expf(u1 - um))) * 0.125f;
        out[bidx] = rho;
    }
}

// ---------------- launch ----------------
extern "C" void kernel_launch(void* const* d_in, const int* in_sizes, int n_in,
                              void* d_out, int out_size) {
    const float* pos0 = (const float*)d_in[0];
    const float* wind = (const float*)d_in[1];
    const float* w1   = (const float*)d_in[2];
    const float* b1   = (const float*)d_in[3];
    const float* w2   = (const float*)d_in[4];
    const float* b2   = (const float*)d_in[5];
    const float* w3   = (const float*)d_in[6];
    const float* b3   = (const float*)d_in[7];
    const float* wmu  = (const float*)d_in[8];
    const float* bmu  = (const float*)d_in[9];
    float* out = (float*)d_out;

    cudaFuncSetAttribute(rollout_kernel,
                         cudaFuncAttributeMaxDynamicSharedMemorySize, SMEM_BYTES);

    prep_w<<<17, 256>>>(w1, w2, w3);

    int B = in_sizes[0] / 2;            // 32768
    int grid = B / 64;                  // 512
    rollout_kernel<<<grid, NTH, SMEM_BYTES>>>(pos0, wind, b1, b2, b3,
                                              wmu, bmu, out);
}

// round 16
// speedup vs baseline: 7.9666x; 1.0602x over previous
#include <cuda_runtime.h>
#include <cuda_fp16.h>
#include <math.h>
#include <stdint.h>

#define NTH 256
#define HOR 64

// ---------------- smem word offsets (64-row tile, fp16 A, 3 W buffers) --------
#define APW    132u                 // A row pitch (words); conflict-free (528B%128=16)
#define BB_W   8448u                // 3 x BSZ_W fp16 W buffers
#define BSZ_W  5120u                // 256 rows * 20 words
#define BPW    20u                  // B row pitch words (80B -> conflict-free ldsm)
#define B1W    23808u
#define B2W    24064u
#define B3W    24320u
#define WMUW   24576u               // [2][256]
#define ACTW   25088u               // [4][64][2] floats
#define SMEM_WORDS 25600u
#define SMEM_BYTES (SMEM_WORDS * 4u)   // 102400 B -> 2 CTAs/SM

// item = 20KB = 5120 words (fp16 W image); 17 items (w1, w2 c0..7, w3 c0..7)
#define ITEM_W 5120u
__device__ uint32_t g_wbuf[17 * 5120];

// ---------------- fp16 helpers ----------------
__device__ __forceinline__ uint32_t pk16(float lo, float hi) {
    __half2 h = __floats2half2_rn(lo, hi);
    return *reinterpret_cast<uint32_t*>(&h);
}

__device__ __forceinline__ uint32_t smem_u32(const void* p) {
    uint32_t a;
    asm("{ .reg .u64 t; cvta.to.shared.u64 t, %1; cvt.u32.u64 %0, t; }" : "=r"(a) : "l"(p));
    return a;
}
__device__ __forceinline__ void mma16816(float& c0, float& c1, float& c2, float& c3,
                                         uint32_t a0, uint32_t a1, uint32_t a2, uint32_t a3,
                                         uint32_t b0, uint32_t b1) {
    asm volatile("mma.sync.aligned.m16n8k16.row.col.f32.f16.f16.f32 "
        "{%0,%1,%2,%3}, {%4,%5,%6,%7}, {%8,%9}, {%0,%1,%2,%3};"
        : "+f"(c0), "+f"(c1), "+f"(c2), "+f"(c3)
        : "r"(a0), "r"(a1), "r"(a2), "r"(a3), "r"(b0), "r"(b1));
}
__device__ __forceinline__ void ldsm4(uint32_t& r0, uint32_t& r1, uint32_t& r2, uint32_t& r3,
                                      uint32_t addr) {
    asm volatile("ldmatrix.sync.aligned.m8n8.x4.shared.b16 {%0,%1,%2,%3}, [%4];"
        : "=r"(r0), "=r"(r1), "=r"(r2), "=r"(r3) : "r"(addr));
}

// ---------------- prep kernel: fp32 W -> fp16 smem-image ----------------
__global__ void prep_w(const float* __restrict__ w1, const float* __restrict__ w2,
                       const float* __restrict__ w3) {
    const int b = blockIdx.x;       // item 0..16
    const int n = threadIdx.x;      // 0..255
    uint32_t* dst = g_wbuf + (uint32_t)b * ITEM_W + (uint32_t)n * BPW;
    float v[32];
    int nk;
    if (b == 0) {
        nk = 16;
#pragma unroll
        for (int k = 0; k < 16; ++k) v[k] = (k < 13) ? w1[k * 256 + n] : 0.0f;
    } else {
        nk = 32;
        const float* W = (b <= 8) ? w2 : w3;
        const int k0 = ((b - 1) & 7) * 32;
#pragma unroll
        for (int k = 0; k < 32; ++k) v[k] = W[(k0 + k) * 256 + n];
    }
    const int nw = nk >> 1;
    for (int wd = 0; wd < nw; ++wd) dst[wd] = pk16(v[2 * wd], v[2 * wd + 1]);
    for (int wd = nw; wd < (int)BPW; ++wd) dst[wd] = 0u;
}

// ---------------- cp.async: one 20KB item -> buffer nbp (0..2) -----------------
__device__ __forceinline__ void stage_item(uint32_t sbase, uint32_t item, uint32_t nbp, int tid) {
    const uint32_t dst = sbase + 4u * (BB_W + nbp * BSZ_W) + (uint32_t)tid * 16u;
    const uint32_t* src = g_wbuf + item * ITEM_W + (uint32_t)tid * 4u;
#pragma unroll
    for (int i = 0; i < 5; ++i)
        asm volatile("cp.async.ca.shared.global [%0], [%1], 16;"
                     :: "r"(dst + 4096u * i), "l"(src + 1024u * i) : "memory");
    asm volatile("cp.async.commit_group;" ::: "memory");
}
#define CP_WAIT1() asm volatile("cp.async.wait_group 1;" ::: "memory")

// ---------------- MMA over one k-chunk: warp tile m32 x n64, NQ k16 steps ----------
template <int NQ>
__device__ __forceinline__ void mma_chunk(float (&c)[2][8][4],
                                          uint32_t aB, uint32_t bB) {
#pragma unroll
    for (int q = 0; q < NQ; ++q) {
        uint32_t a00, a01, a02, a03, a10, a11, a12, a13;
        ldsm4(a00, a01, a02, a03, aB + 32u * q);            // m-block p=0
        ldsm4(a10, a11, a12, a13, aB + 8448u + 32u * q);    // p=1 (+16 rows * 132w * 4B)
#pragma unroll
        for (int jp = 0; jp < 4; ++jp) {
            const uint32_t off = 1280u * (uint32_t)jp + 32u * q;
            uint32_t b0, b1, b2, b3;
            ldsm4(b0, b1, b2, b3, bB + off);
            mma16816(c[0][2*jp][0],   c[0][2*jp][1],   c[0][2*jp][2],   c[0][2*jp][3],
                     a00, a01, a02, a03, b0, b1);
            mma16816(c[0][2*jp+1][0], c[0][2*jp+1][1], c[0][2*jp+1][2], c[0][2*jp+1][3],
                     a00, a01, a02, a03, b2, b3);
            mma16816(c[1][2*jp][0],   c[1][2*jp][1],   c[1][2*jp][2],   c[1][2*jp][3],
                     a10, a11, a12, a13, b0, b1);
            mma16816(c[1][2*jp+1][0], c[1][2*jp+1][1], c[1][2*jp+1][2], c[1][2*jp+1][3],
                     a10, a11, a12, a13, b2, b3);
        }
    }
}

// h = relu(C + bias) -> A smem (fp16); zero C
__device__ __forceinline__ void epi_h(float (&c)[2][8][4], const float* __restrict__ smem,
                                      uint32_t* __restrict__ smw, uint32_t bW,
                                      int wm, int wn, int g, int tg) {
#pragma unroll
    for (int p = 0; p < 2; ++p) {
        const uint32_t r0w = (uint32_t)(32 * wm + 16 * p + g) * APW;
        const uint32_t r1w = r0w + 8u * APW;
#pragma unroll
        for (int j = 0; j < 8; ++j) {
            const int n = 64 * wn + 8 * j + 2 * tg;
            float2 bb = *reinterpret_cast<const float2*>(smem + bW + n);
            float v0 = fmaxf(c[p][j][0] + bb.x, 0.0f), v1 = fmaxf(c[p][j][1] + bb.y, 0.0f);
            float v2 = fmaxf(c[p][j][2] + bb.x, 0.0f), v3 = fmaxf(c[p][j][3] + bb.y, 0.0f);
            const uint32_t wof = (uint32_t)(n >> 1);
            smw[r0w + wof] = pk16(v0, v1);
            smw[r1w + wof] = pk16(v2, v3);
            c[p][j][0] = c[p][j][1] = c[p][j][2] = c[p][j][3] = 0.0f;
        }
    }
}

// ---------------- main kernel ----------------
__global__ void __launch_bounds__(NTH, 2)
rollout_kernel(const float* __restrict__ pos0, const float* __restrict__ wind,
               const float* __restrict__ b1, const float* __restrict__ b2,
               const float* __restrict__ b3,
               const float* __restrict__ wmu, const float* __restrict__ bmu,
               float* __restrict__ out) {
    extern __shared__ float smem[];
    uint32_t* smw = reinterpret_cast<uint32_t*>(smem);
    const uint32_t sbase = smem_u32(smem);

    const int tid = threadIdx.x;
    const int w = tid >> 5, l = tid & 31;
    const int wm = w & 1, wn = w >> 1;      // 2 m-blocks x 4 n-quarters
    const int g = l >> 2, tg = l & 3;

    // ldmatrix lane addresses (bytes)
    const int mlane = 32 * wm + 8 * ((l >> 3) & 1) + (l & 7);
    const uint32_t aB = sbase + 4u * ((uint32_t)mlane * APW + 4u * (uint32_t)(l >> 4));
    const uint32_t bLaneW = ((uint32_t)(64 * wn + 8 * (l >> 4) + (l & 7))) * BPW
                          + 4u * (uint32_t)((l >> 3) & 1);

    // constants -> smem
    smem[B1W + tid] = b1[tid];
    smem[B2W + tid] = b2[tid];
    smem[B3W + tid] = b3[tid];
    smem[WMUW + tid]        = wmu[tid * 2];
    smem[WMUW + 256 + tid]  = wmu[tid * 2 + 1];
    const float bmu0 = __ldg(bmu), bmu1 = __ldg(bmu + 1);

    // per-element state: thread tid<64 owns batch element
    const int bidx = blockIdx.x * 64 + tid;
    const bool owner = (tid < 64);
    float px = 0.f, py = 0.f, wxv = 0.f, wyv = 0.f;
    float msafe = -INFINITY, ssafe = 0.f, mreach = -INFINITY, sreach = 0.f;
    if (owner) {
        px = pos0[2 * bidx]; py = pos0[2 * bidx + 1];
        wxv = wind[2 * bidx]; wyv = wind[2 * bidx + 1];
    }
    const float ox0 = 1.75f, oy0 = 1.75f, r0c = 0.38f;
    const float ox1 = 1.75f, oy1 = 3.75f, r1c = 0.42f;
    const float ox2 = 3.75f, oy2 = 2.00f, r2c = 0.34f;

    // prologue: stage g=0 (item0 -> buf0) and g=1 (item1 -> buf1)
    stage_item(sbase, 0u, 0u, tid);
    stage_item(sbase, 1u, 1u, tid);

    float cf[2][8][4];
#pragma unroll
    for (int p = 0; p < 2; ++p)
#pragma unroll
        for (int j = 0; j < 8; ++j)
#pragma unroll
            for (int q = 0; q < 4; ++q) cf[p][j][q] = 0.0f;

    uint32_t cb = 0;   // buffer of current chunk = (t*17 + j) % 3

#pragma unroll 1
    for (int t = 0; t < HOR; ++t) {
        // ---- obs -> A rows (k 0..15, fp16); ordered vs mma by j=0 sync ----
        if (owner) {
            float o[16];
            o[0] = px * 0.1f; o[1] = py * 0.1f;
            o[2] = (4.0f - px) * 0.1f; o[3] = (3.0f - py) * 0.1f;
            float dx0 = px - ox0, dy0 = py - oy0;
            float dx1 = px - ox1, dy1 = py - oy1;
            float dx2 = px - ox2, dy2 = py - oy2;
            float d0 = sqrtf(dx0 * dx0 + dy0 * dy0 + 1e-9f);
            float d1 = sqrtf(dx1 * dx1 + dy1 * dy1 + 1e-9f);
            float d2 = sqrtf(dx2 * dx2 + dy2 * dy2 + 1e-9f);
            o[4] = -dx0 * 0.1f; o[5] = -dy0 * 0.1f;
            o[6] = -dx1 * 0.1f; o[7] = -dy1 * 0.1f;
            o[8] = -dx2 * 0.1f; o[9] = -dy2 * 0.1f;
            o[10] = d0 - r0c; o[11] = d1 - r1c; o[12] = d2 - r2c;
            o[13] = 0.f; o[14] = 0.f; o[15] = 0.f;
            const uint32_t mb = (uint32_t)tid * APW;
#pragma unroll
            for (int i = 0; i < 8; ++i) smw[mb + i] = pk16(o[2 * i], o[2 * i + 1]);
        }

        // ---- 17 chunks: j=0 L1(w1), j=1..8 L2(w2), j=9..16 L3(w3) ----
#pragma unroll 1
        for (int j = 0; j < 17; ++j) {
            CP_WAIT1();                 // group for chunk (t*17+j) committed 2 iters ago -> done
            __syncthreads();            // publish buffer cb; recycle guard; orders obs/epi
            if (j == 1) { epi_h(cf, smem, smw, B1W, wm, wn, g, tg); __syncthreads(); }
            if (j == 9) { epi_h(cf, smem, smw, B2W, wm, wn, g, tg); __syncthreads(); }
            const uint32_t bh = sbase + 4u * (BB_W + cb * BSZ_W + bLaneW);
            if (j == 0) mma_chunk<1>(cf, aB, bh);
            else        mma_chunk<2>(cf, aB + 64u * (uint32_t)((j - 1) & 7), bh);
            // stage chunk g+2 (item (j+2)%17) into buffer (cb+2)%3 — safe post-sync
            uint32_t nit = (uint32_t)(j + 2);
            if (nit >= 17u) nit -= 17u;
            uint32_t nb = cb + 2u;
            if (nb >= 3u) nb -= 3u;
            stage_item(sbase, nit, nb, tid);
            cb = (cb + 1u == 3u) ? 0u : cb + 1u;
        }

        // ---- actions: clip(relu(C+b3) @ wmu + bmu), reduce over 4 n-quarters ----
        {
#pragma unroll
            for (int p = 0; p < 2; ++p) {
                float p00 = 0.f, p01 = 0.f, p10 = 0.f, p11 = 0.f;
#pragma unroll
                for (int j = 0; j < 8; ++j) {
                    const int n = 64 * wn + 8 * j + 2 * tg;
                    float2 bb = *reinterpret_cast<const float2*>(smem + B3W + n);
                    float v0 = fmaxf(cf[p][j][0] + bb.x, 0.f), v1 = fmaxf(cf[p][j][1] + bb.y, 0.f);
                    float v2 = fmaxf(cf[p][j][2] + bb.x, 0.f), v3 = fmaxf(cf[p][j][3] + bb.y, 0.f);
                    float2 u0 = *reinterpret_cast<const float2*>(smem + WMUW + n);
                    float2 u1 = *reinterpret_cast<const float2*>(smem + WMUW + 256 + n);
                    p00 = fmaf(v0, u0.x, fmaf(v1, u0.y, p00));
                    p01 = fmaf(v0, u1.x, fmaf(v1, u1.y, p01));
                    p10 = fmaf(v2, u0.x, fmaf(v3, u0.y, p10));
                    p11 = fmaf(v2, u1.x, fmaf(v3, u1.y, p11));
                    cf[p][j][0] = cf[p][j][1] = cf[p][j][2] = cf[p][j][3] = 0.f;
                }
                p00 += __shfl_xor_sync(0xffffffffu, p00, 1);
                p00 += __shfl_xor_sync(0xffffffffu, p00, 2);
                p01 += __shfl_xor_sync(0xffffffffu, p01, 1);
                p01 += __shfl_xor_sync(0xffffffffu, p01, 2);
                p10 += __shfl_xor_sync(0xffffffffu, p10, 1);
                p10 += __shfl_xor_sync(0xffffffffu, p10, 2);
                p11 += __shfl_xor_sync(0xffffffffu, p11, 1);
                p11 += __shfl_xor_sync(0xffffffffu, p11, 2);
                if (tg == 0) {
                    const int m0 = 32 * wm + 16 * p + g;
                    *reinterpret_cast<float2*>(smem + ACTW + wn * 128 + 2 * m0) =
                        make_float2(p00, p01);
                    *reinterpret_cast<float2*>(smem + ACTW + wn * 128 + 2 * (m0 + 8)) =
                        make_float2(p10, p11);
                }
            }
        }
        __syncthreads();

        // ---- dynamics + streaming STREL stats ----
        if (owner) {
            float2 a0 = *reinterpret_cast<const float2*>(smem + ACTW + 2 * tid);
            float2 a1 = *reinterpret_cast<const float2*>(smem + ACTW + 128 + 2 * tid);
            float2 a2 = *reinterpret_cast<const float2*>(smem + ACTW + 256 + 2 * tid);
            float2 a3 = *reinterpret_cast<const float2*>(smem + ACTW + 384 + 2 * tid);
            float ax = fminf(fmaxf(a0.x + a1.x + a2.x + a3.x + bmu0, -1.0f), 1.0f);
            float ay = fminf(fmaxf(a0.y + a1.y + a2.y + a3.y + bmu1, -1.0f), 1.0f);
            float vx = 2.0f * ax + wxv;
            float vy = 2.0f * ay + wyv;
#pragma unroll
            for (int s = 0; s < 4; ++s) {
                px = fminf(fmaxf(px + 0.0625f * vx, -4.0f), 10.0f);
                py = fminf(fmaxf(py + 0.0625f * vy, -4.0f), 10.0f);
            }
            float dx0 = px - ox0, dy0 = py - oy0;
            float dx1 = px - ox1, dy1 = py - oy1;
            float dx2 = px - ox2, dy2 = py - oy2;
            float c0 = sqrtf(dx0 * dx0 + dy0 * dy0 + 1e-9f) - r0c;
            float c1 = sqrtf(dx1 * dx1 + dy1 * dy1 + 1e-9f) - r1c;
            float c2 = sqrtf(dx2 * dx2 + dy2 * dy2 + 1e-9f) - r2c;
            float v0 = -50.0f * c0, v1 = -50.0f * c1, v2 = -50.0f * c2;
            float vm = fmaxf(v0, fmaxf(v1, v2));
            float lse = vm + logf(expf(v0 - vm) + expf(v1 - vm) + expf(v2 - vm));
            float safe = -lse / 50.0f;
            float vs = -8.0f * safe;
            if (vs > msafe) { ssafe = ssafe * expf(msafe - vs) + 1.0f; msafe = vs; }
            else            { ssafe += expf(vs - msafe); }
            float gdx = px - 4.0f, gdy = py - 3.0f;
            float gd = sqrtf(gdx * gdx + gdy * gdy + 1e-9f);
            float vr = 8.0f * (0.45f - gd);
            if (vr > mreach) { sreach = sreach * expf(mreach - vr) + 1.0f; mreach = vr; }
            else             { sreach += expf(vr - mreach); }
        }
    }

    if (owner) {
        float rs = -(msafe + logf(ssafe)) * 0.125f;
        float rr = (mreach + logf(sreach)) * 0.125f;
        float u0 = -8.0f * rs, u1 = -8.0f * rr;
        float um = fmaxf(u0, u1);
        float rho = -(um + logf(expf(u0 - um) + expf(u1 - um))) * 0.125f;
        out[bidx] = rho;
    }
}

// ---------------- launch ----------------
extern "C" void kernel_launch(void* const* d_in, const int* in_sizes, int n_in,
                              void* d_out, int out_size) {
    const float* pos0 = (const float*)d_in[0];
    const float* wind = (const float*)d_in[1];
    const float* w1   = (const float*)d_in[2];
    const float* b1   = (const float*)d_in[3];
    const float* w2   = (const float*)d_in[4];
    const float* b2   = (const float*)d_in[5];
    const float* w3   = (const float*)d_in[6];
    const float* b3   = (const float*)d_in[7];
    const float* wmu  = (const float*)d_in[8];
    const float* bmu  = (const float*)d_in[9];
    float* out = (float*)d_out;

    cudaFuncSetAttribute(rollout_kernel,
                         cudaFuncAttributeMaxDynamicSharedMemorySize, SMEM_BYTES);

    prep_w<<<17, 256>>>(w1, w2, w3);

    int B = in_sizes[0] / 2;            // 32768
    int grid = B / 64;                  // 512
    rollout_kernel<<<grid, NTH, SMEM_BYTES>>>(pos0, wind, b1, b2, b3,
                                              wmu, bmu, out);
}

// round 17
// speedup vs baseline: 9.4066x; 1.1808x over previous
#include <cuda_runtime.h>
#include <cuda_fp16.h>
#include <math.h>
#include <stdint.h>

#define NTH 128
#define HOR 64

// ---------------- smem word offsets (64-row tile, fp16 A, 3 W buffers) --------
#define APW    132u                 // A row pitch (words); conflict-free
#define BB_W   8448u                // 3 x BSZ_W fp16 W buffers
#define BSZ_W  5120u                // 256 rows * 20 words
#define BPW    20u                  // B row pitch words (80B, 16B-aligned rows)
#define B1W    23808u
#define B2W    24064u
#define B3W    24320u
#define WMUW   24576u               // [2][256]
#define ACTW   25088u               // [4][64][2] floats
#define SMEM_WORDS 25600u
#define SMEM_BYTES (SMEM_WORDS * 4u)   // 102400 B -> 2 CTAs/SM

// item = 20KB = 5120 words (fp16 W image); 17 items (w1, w2 c0..7, w3 c0..7)
#define ITEM_W 5120u
__device__ uint32_t g_wbuf[17 * 5120];

// ---------------- fp16 helpers ----------------
__device__ __forceinline__ uint32_t pk16(float lo, float hi) {
    __half2 h = __floats2half2_rn(lo, hi);
    return *reinterpret_cast<uint32_t*>(&h);
}

__device__ __forceinline__ uint32_t smem_u32(const void* p) {
    uint32_t a;
    asm("{ .reg .u64 t; cvta.to.shared.u64 t, %1; cvt.u32.u64 %0, t; }" : "=r"(a) : "l"(p));
    return a;
}
__device__ __forceinline__ void mma16816(float& c0, float& c1, float& c2, float& c3,
                                         uint32_t a0, uint32_t a1, uint32_t a2, uint32_t a3,
                                         uint32_t b0, uint32_t b1) {
    asm volatile("mma.sync.aligned.m16n8k16.row.col.f32.f16.f16.f32 "
        "{%0,%1,%2,%3}, {%4,%5,%6,%7}, {%8,%9}, {%0,%1,%2,%3};"
        : "+f"(c0), "+f"(c1), "+f"(c2), "+f"(c3)
        : "r"(a0), "r"(a1), "r"(a2), "r"(a3), "r"(b0), "r"(b1));
}
__device__ __forceinline__ void ldsm4(uint32_t& r0, uint32_t& r1, uint32_t& r2, uint32_t& r3,
                                      uint32_t addr) {
    asm volatile("ldmatrix.sync.aligned.m8n8.x4.shared.b16 {%0,%1,%2,%3}, [%4];"
        : "=r"(r0), "=r"(r1), "=r"(r2), "=r"(r3) : "r"(addr));
}

// ---------------- prep kernel: fp32 W -> fp16 smem-image ----------------
__global__ void prep_w(const float* __restrict__ w1, const float* __restrict__ w2,
                       const float* __restrict__ w3) {
    const int b = blockIdx.x;       // item 0..16
    const int n = threadIdx.x;      // 0..255
    uint32_t* dst = g_wbuf + (uint32_t)b * ITEM_W + (uint32_t)n * BPW;
    float v[32];
    int nk;
    if (b == 0) {
        nk = 16;
#pragma unroll
        for (int k = 0; k < 16; ++k) v[k] = (k < 13) ? w1[k * 256 + n] : 0.0f;
    } else {
        nk = 32;
        const float* W = (b <= 8) ? w2 : w3;
        const int k0 = ((b - 1) & 7) * 32;
#pragma unroll
        for (int k = 0; k < 32; ++k) v[k] = W[(k0 + k) * 256 + n];
    }
    const int nw = nk >> 1;
    for (int wd = 0; wd < nw; ++wd) dst[wd] = pk16(v[2 * wd], v[2 * wd + 1]);
    for (int wd = nw; wd < (int)BPW; ++wd) dst[wd] = 0u;
}

// ---------------- cp.async: one 20KB item -> buffer nbp (0..2), 128 threads ----
__device__ __forceinline__ void stage_item(uint32_t sbase, uint32_t item, uint32_t nbp, int tid) {
    const uint32_t dst = sbase + 4u * (BB_W + nbp * BSZ_W) + (uint32_t)tid * 16u;
    const uint32_t* src = g_wbuf + item * ITEM_W + (uint32_t)tid * 4u;
#pragma unroll
    for (int i = 0; i < 10; ++i)
        asm volatile("cp.async.ca.shared.global [%0], [%1], 16;"
                     :: "r"(dst + 2048u * i), "l"(src + 512u * i) : "memory");
    asm volatile("cp.async.commit_group;" ::: "memory");
}
#define CP_WAIT1() asm volatile("cp.async.wait_group 1;" ::: "memory")

// ---------------- MMA over one k-chunk: warp tile m64 x n64, NQ k16 steps ------
// c[mb][j][4]: mb = m16 block (rows 16mb..), j = n8 tile (cols 64wn+8j)
template <int NQ>
__device__ __forceinline__ void mma_chunk(float (&c)[4][8][4],
                                          uint32_t aB, uint32_t bB) {
#pragma unroll
    for (int q = 0; q < NQ; ++q) {
        uint32_t a[4][4];
#pragma unroll
        for (int mb = 0; mb < 4; ++mb)
            ldsm4(a[mb][0], a[mb][1], a[mb][2], a[mb][3], aB + 8448u * mb + 32u * q);
#pragma unroll
        for (int jp = 0; jp < 4; ++jp) {
            const uint32_t off = 1280u * (uint32_t)jp + 32u * q;
            uint32_t b0, b1, b2, b3;
            ldsm4(b0, b1, b2, b3, bB + off);
#pragma unroll
            for (int mb = 0; mb < 4; ++mb) {
                mma16816(c[mb][2*jp][0],   c[mb][2*jp][1],   c[mb][2*jp][2],   c[mb][2*jp][3],
                         a[mb][0], a[mb][1], a[mb][2], a[mb][3], b0, b1);
                mma16816(c[mb][2*jp+1][0], c[mb][2*jp+1][1], c[mb][2*jp+1][2], c[mb][2*jp+1][3],
                         a[mb][0], a[mb][1], a[mb][2], a[mb][3], b2, b3);
            }
        }
    }
}

// h = relu(C + bias) -> A smem (fp16); zero C
__device__ __forceinline__ void epi_h(float (&c)[4][8][4], const float* __restrict__ smem,
                                      uint32_t* __restrict__ smw, uint32_t bW,
                                      int wn, int g, int tg) {
#pragma unroll
    for (int mb = 0; mb < 4; ++mb) {
        const uint32_t r0w = (uint32_t)(16 * mb + g) * APW;
        const uint32_t r1w = r0w + 8u * APW;
#pragma unroll
        for (int j = 0; j < 8; ++j) {
            const int n = 64 * wn + 8 * j + 2 * tg;
            float2 bb = *reinterpret_cast<const float2*>(smem + bW + n);
            float v0 = fmaxf(c[mb][j][0] + bb.x, 0.0f), v1 = fmaxf(c[mb][j][1] + bb.y, 0.0f);
            float v2 = fmaxf(c[mb][j][2] + bb.x, 0.0f), v3 = fmaxf(c[mb][j][3] + bb.y, 0.0f);
            const uint32_t wof = (uint32_t)(n >> 1);
            smw[r0w + wof] = pk16(v0, v1);
            smw[r1w + wof] = pk16(v2, v3);
            c[mb][j][0] = c[mb][j][1] = c[mb][j][2] = c[mb][j][3] = 0.0f;
        }
    }
}

// ---------------- main kernel ----------------
__global__ void __launch_bounds__(NTH, 2)
rollout_kernel(const float* __restrict__ pos0, const float* __restrict__ wind,
               const float* __restrict__ b1, const float* __restrict__ b2,
               const float* __restrict__ b3,
               const float* __restrict__ wmu, const float* __restrict__ bmu,
               float* __restrict__ out) {
    extern __shared__ float smem[];
    uint32_t* smw = reinterpret_cast<uint32_t*>(smem);
    const uint32_t sbase = smem_u32(smem);

    const int tid = threadIdx.x;
    const int wn = tid >> 5, l = tid & 31;   // 4 warps, one n-quarter each
    const int g = l >> 2, tg = l & 3;

    // ldmatrix lane addresses (bytes)
    const int mlane = 8 * ((l >> 3) & 1) + (l & 7);   // m-block-relative row
    const uint32_t aB = sbase + 4u * ((uint32_t)mlane * APW + 4u * (uint32_t)(l >> 4));
    const uint32_t bLaneW = ((uint32_t)(64 * wn + 8 * (l >> 4) + (l & 7))) * BPW
                          + 4u * (uint32_t)((l >> 3) & 1);

    // constants -> smem (128 threads cover 256 entries in 2 passes)
#pragma unroll
    for (int i = 0; i < 2; ++i) {
        int idx = tid + 128 * i;
        smem[B1W + idx] = b1[idx];
        smem[B2W + idx] = b2[idx];
        smem[B3W + idx] = b3[idx];
        smem[WMUW + idx]       = wmu[idx * 2];
        smem[WMUW + 256 + idx] = wmu[idx * 2 + 1];
    }
    const float bmu0 = __ldg(bmu), bmu1 = __ldg(bmu + 1);

    // per-element state: thread tid<64 owns batch element
    const int bidx = blockIdx.x * 64 + tid;
    const bool owner = (tid < 64);
    float px = 0.f, py = 0.f, wxv = 0.f, wyv = 0.f;
    float msafe = -INFINITY, ssafe = 0.f, mreach = -INFINITY, sreach = 0.f;
    if (owner) {
        px = pos0[2 * bidx]; py = pos0[2 * bidx + 1];
        wxv = wind[2 * bidx]; wyv = wind[2 * bidx + 1];
    }
    const float ox0 = 1.75f, oy0 = 1.75f, r0c = 0.38f;
    const float ox1 = 1.75f, oy1 = 3.75f, r1c = 0.42f;
    const float ox2 = 3.75f, oy2 = 2.00f, r2c = 0.34f;

    // prologue: stage g=0 (item0 -> buf0) and g=1 (item1 -> buf1)
    stage_item(sbase, 0u, 0u, tid);
    stage_item(sbase, 1u, 1u, tid);

    float cf[4][8][4];
#pragma unroll
    for (int mb = 0; mb < 4; ++mb)
#pragma unroll
        for (int j = 0; j < 8; ++j)
#pragma unroll
            for (int q = 0; q < 4; ++q) cf[mb][j][q] = 0.0f;

    uint32_t cb = 0;   // buffer of current chunk = (t*17 + j) % 3

#pragma unroll 1
    for (int t = 0; t < HOR; ++t) {
        // ---- obs -> A rows (k 0..15, fp16); ordered vs mma by j=0 sync ----
        if (owner) {
            float o[16];
            o[0] = px * 0.1f; o[1] = py * 0.1f;
            o[2] = (4.0f - px) * 0.1f; o[3] = (3.0f - py) * 0.1f;
            float dx0 = px - ox0, dy0 = py - oy0;
            float dx1 = px - ox1, dy1 = py - oy1;
            float dx2 = px - ox2, dy2 = py - oy2;
            float d0 = sqrtf(dx0 * dx0 + dy0 * dy0 + 1e-9f);
            float d1 = sqrtf(dx1 * dx1 + dy1 * dy1 + 1e-9f);
            float d2 = sqrtf(dx2 * dx2 + dy2 * dy2 + 1e-9f);
            o[4] = -dx0 * 0.1f; o[5] = -dy0 * 0.1f;
            o[6] = -dx1 * 0.1f; o[7] = -dy1 * 0.1f;
            o[8] = -dx2 * 0.1f; o[9] = -dy2 * 0.1f;
            o[10] = d0 - r0c; o[11] = d1 - r1c; o[12] = d2 - r2c;
            o[13] = 0.f; o[14] = 0.f; o[15] = 0.f;
            const uint32_t mb = (uint32_t)tid * APW;
#pragma unroll
            for (int i = 0; i < 8; ++i) smw[mb + i] = pk16(o[2 * i], o[2 * i + 1]);
        }

        // ---- 17 chunks: j=0 L1(w1), j=1..8 L2(w2), j=9..16 L3(w3) ----
#pragma unroll 1
        for (int j = 0; j < 17; ++j) {
            CP_WAIT1();                 // group for this chunk committed 2 iters ago
            __syncthreads();            // publish buffer cb; recycle guard; orders obs/epi
            if (j == 1) { epi_h(cf, smem, smw, B1W, wn, g, tg); __syncthreads(); }
            if (j == 9) { epi_h(cf, smem, smw, B2W, wn, g, tg); __syncthreads(); }
            const uint32_t bh = sbase + 4u * (BB_W + cb * BSZ_W + bLaneW);
            if (j == 0) mma_chunk<1>(cf, aB, bh);
            else        mma_chunk<2>(cf, aB + 64u * (uint32_t)((j - 1) & 7), bh);
            // stage chunk g+2 (item (j+2)%17) into buffer (cb+2)%3
            uint32_t nit = (uint32_t)(j + 2);
            if (nit >= 17u) nit -= 17u;
            uint32_t nb = cb + 2u;
            if (nb >= 3u) nb -= 3u;
            stage_item(sbase, nit, nb, tid);
            cb = (cb + 1u == 3u) ? 0u : cb + 1u;
        }

        // ---- actions: clip(relu(C+b3) @ wmu + bmu), reduce over 4 n-quarters ----
        {
#pragma unroll
            for (int mb = 0; mb < 4; ++mb) {
                float p00 = 0.f, p01 = 0.f, p10 = 0.f, p11 = 0.f;
#pragma unroll
                for (int j = 0; j < 8; ++j) {
                    const int n = 64 * wn + 8 * j + 2 * tg;
                    float2 bb = *reinterpret_cast<const float2*>(smem + B3W + n);
                    float v0 = fmaxf(cf[mb][j][0] + bb.x, 0.f), v1 = fmaxf(cf[mb][j][1] + bb.y, 0.f);
                    float v2 = fmaxf(cf[mb][j][2] + bb.x, 0.f), v3 = fmaxf(cf[mb][j][3] + bb.y, 0.f);
                    float2 u0 = *reinterpret_cast<const float2*>(smem + WMUW + n);
                    float2 u1 = *reinterpret_cast<const float2*>(smem + WMUW + 256 + n);
                    p00 = fmaf(v0, u0.x, fmaf(v1, u0.y, p00));
                    p01 = fmaf(v0, u1.x, fmaf(v1, u1.y, p01));
                    p10 = fmaf(v2, u0.x, fmaf(v3, u0.y, p10));
                    p11 = fmaf(v2, u1.x, fmaf(v3, u1.y, p11));
                    cf[mb][j][0] = cf[mb][j][1] = cf[mb][j][2] = cf[mb][j][3] = 0.f;
                }
                p00 += __shfl_xor_sync(0xffffffffu, p00, 1);
                p00 += __shfl_xor_sync(0xffffffffu, p00, 2);
                p01 += __shfl_xor_sync(0xffffffffu, p01, 1);
                p01 += __shfl_xor_sync(0xffffffffu, p01, 2);
                p10 += __shfl_xor_sync(0xffffffffu, p10, 1);
                p10 += __shfl_xor_sync(0xffffffffu, p10, 2);
                p11 += __shfl_xor_sync(0xffffffffu, p11, 1);
                p11 += __shfl_xor_sync(0xffffffffu, p11, 2);
                if (tg == 0) {
                    const int m0 = 16 * mb + g;
                    *reinterpret_cast<float2*>(smem + ACTW + wn * 128 + 2 * m0) =
                        make_float2(p00, p01);
                    *reinterpret_cast<float2*>(smem + ACTW + wn * 128 + 2 * (m0 + 8)) =
                        make_float2(p10, p11);
                }
            }
        }
        __syncthreads();

        // ---- dynamics + streaming STREL stats ----
        if (owner) {
            float2 a0 = *reinterpret_cast<const float2*>(smem + ACTW + 2 * tid);
            float2 a1 = *reinterpret_cast<const float2*>(smem + ACTW + 128 + 2 * tid);
            float2 a2 = *reinterpret_cast<const float2*>(smem + ACTW + 256 + 2 * tid);
            float2 a3 = *reinterpret_cast<const float2*>(smem + ACTW + 384 + 2 * tid);
            float ax = fminf(fmaxf(a0.x + a1.x + a2.x + a3.x + bmu0, -1.0f), 1.0f);
            float ay = fminf(fmaxf(a0.y + a1.y + a2.y + a3.y + bmu1, -1.0f), 1.0f);
            float vx = 2.0f * ax + wxv;
            float vy = 2.0f * ay + wyv;
#pragma unroll
            for (int s = 0; s < 4; ++s) {
                px = fminf(fmaxf(px + 0.0625f * vx, -4.0f), 10.0f);
                py = fminf(fmaxf(py + 0.0625f * vy, -4.0f), 10.0f);
            }
            float dx0 = px - ox0, dy0 = py - oy0;
            float dx1 = px - ox1, dy1 = py - oy1;
            float dx2 = px - ox2, dy2 = py - oy2;
            float c0 = sqrtf(dx0 * dx0 + dy0 * dy0 + 1e-9f) - r0c;
            float c1 = sqrtf(dx1 * dx1 + dy1 * dy1 + 1e-9f) - r1c;
            float c2 = sqrtf(dx2 * dx2 + dy2 * dy2 + 1e-9f) - r2c;
            float v0 = -50.0f * c0, v1 = -50.0f * c1, v2 = -50.0f * c2;
            float vm = fmaxf(v0, fmaxf(v1, v2));
            float lse = vm + logf(expf(v0 - vm) + expf(v1 - vm) + expf(v2 - vm));
            float safe = -lse / 50.0f;
            float vs = -8.0f * safe;
            if (vs > msafe) { ssafe = ssafe * expf(msafe - vs) + 1.0f; msafe = vs; }
            else            { ssafe += expf(vs - msafe); }
            float gdx = px - 4.0f, gdy = py - 3.0f;
            float gd = sqrtf(gdx * gdx + gdy * gdy + 1e-9f);
            float vr = 8.0f * (0.45f - gd);
            if (vr > mreach) { sreach = sreach * expf(mreach - vr) + 1.0f; mreach = vr; }
            else             { sreach += expf(vr - mreach); }
        }
    }

    if (owner) {
        float rs = -(msafe + logf(ssafe)) * 0.125f;
        float rr = (mreach + logf(sreach)) * 0.125f;
        float u0 = -8.0f * rs, u1 = -8.0f * rr;
        float um = fmaxf(u0, u1);
        float rho = -(um + logf(expf(u0 - um) + expf(u1 - um))) * 0.125f;
        out[bidx] = rho;
    }
}

// ---------------- launch ----------------
extern "C" void kernel_launch(void* const* d_in, const int* in_sizes, int n_in,
                              void* d_out, int out_size) {
    const float* pos0 = (const float*)d_in[0];
    const float* wind = (const float*)d_in[1];
    const float* w1   = (const float*)d_in[2];
    const float* b1   = (const float*)d_in[3];
    const float* w2   = (const float*)d_in[4];
    const float* b2   = (const float*)d_in[5];
    const float* w3   = (const float*)d_in[6];
    const float* b3   = (const float*)d_in[7];
    const float* wmu  = (const float*)d_in[8];
    const float* bmu  = (const float*)d_in[9];
    float* out = (float*)d_out;

    cudaFuncSetAttribute(rollout_kernel,
                         cudaFuncAttributeMaxDynamicSharedMemorySize, SMEM_BYTES);

    prep_w<<<17, 256>>>(w1, w2, w3);

    int B = in_sizes[0] / 2;            // 32768
    int grid = B / 64;                  // 512
    rollout_kernel<<<grid, NTH, SMEM_BYTES>>>(pos0, wind, b1, b2, b3,
                                              wmu, bmu, out);
}